// round 3
// baseline (speedup 1.0000x reference)
#include <cuda_runtime.h>
#include <cuda_bf16.h>
#include <math_constants.h>

// ---------------------------------------------------------------------------
// MHA: x[2,2048,1024] -> QKV proj -> 16-head attention -> out proj
// Round 3: fp32. FIX: never pass __device__ symbols from host code.
// The out-projection kernel reads g_O via the device symbol in device code.
// ---------------------------------------------------------------------------

#define B       2
#define S       2048
#define HID     1024
#define HEADS   16
#define HD      64
#define M_TOT   (B * S)            // 4096
#define SCALE   0.125f             // 64^-0.5

// Scratch (device globals: allocation-free rule)
__device__ float g_Q[B * HEADS * S * HD];   // [b*16+h][s][d]
__device__ float g_K[B * HEADS * S * HD];
__device__ float g_V[B * HEADS * S * HD];
__device__ float g_O[M_TOT * HID];          // [b*s][h*64+d]

// ---------------------------------------------------------------------------
// Tiled GEMM: C[m,n] = sum_k A[m,k] * Bw[n,k]   (both K-major)
// BM=BN=64, BK=16, 256 threads, 4x4 per thread.
// MODE 0: A := g_O (device symbol, A arg ignored); C[m*N+n] = acc
// MODE 1: A := x (host-provided); scatter into g_Q/g_K/g_V
// ---------------------------------------------------------------------------
#define SW 68   // smem row stride (floats), 16B aligned

template <int MODE>
__global__ __launch_bounds__(256) void gemm_kernel(
    const float* __restrict__ A_in, const float* __restrict__ Bw,
    float* __restrict__ C, int N, int K)
{
    __shared__ float As[16][SW];
    __shared__ float Bs[16][SW];

    // Device-side reference to the device symbol is legal here.
    const float* __restrict__ A = (MODE == 0) ? (const float*)g_O : A_in;

    const int tid = threadIdx.x;
    const int tx = tid & 15;        // 0..15 -> n
    const int ty = tid >> 4;        // 0..15 -> m
    const int bm = blockIdx.y;
    const int bn = blockIdx.x;

    const int lrow = tid >> 2;      // 0..63
    const int lc4  = tid & 3;       // 0..3  (float4 column)

    const float* Ap = A  + (bm * 64 + lrow) * K + lc4 * 4;
    const float* Bp = Bw + (bn * 64 + lrow) * K + lc4 * 4;

    float acc[4][4];
#pragma unroll
    for (int i = 0; i < 4; i++)
#pragma unroll
        for (int j = 0; j < 4; j++) acc[i][j] = 0.f;

    const int ktiles = K >> 4;
    for (int kt = 0; kt < ktiles; kt++) {
        float4 av = *reinterpret_cast<const float4*>(Ap + kt * 16);
        float4 bv = *reinterpret_cast<const float4*>(Bp + kt * 16);
        As[lc4 * 4 + 0][lrow] = av.x;
        As[lc4 * 4 + 1][lrow] = av.y;
        As[lc4 * 4 + 2][lrow] = av.z;
        As[lc4 * 4 + 3][lrow] = av.w;
        Bs[lc4 * 4 + 0][lrow] = bv.x;
        Bs[lc4 * 4 + 1][lrow] = bv.y;
        Bs[lc4 * 4 + 2][lrow] = bv.z;
        Bs[lc4 * 4 + 3][lrow] = bv.w;
        __syncthreads();

#pragma unroll
        for (int kk = 0; kk < 16; kk++) {
            float4 a4 = *reinterpret_cast<const float4*>(&As[kk][ty * 4]);
            float4 b4 = *reinterpret_cast<const float4*>(&Bs[kk][tx * 4]);
            float ar[4] = {a4.x, a4.y, a4.z, a4.w};
            float br[4] = {b4.x, b4.y, b4.z, b4.w};
#pragma unroll
            for (int i = 0; i < 4; i++)
#pragma unroll
                for (int j = 0; j < 4; j++)
                    acc[i][j] = fmaf(ar[i], br[j], acc[i][j]);
        }
        __syncthreads();
    }

    if (MODE == 0) {
#pragma unroll
        for (int i = 0; i < 4; i++) {
            int m = bm * 64 + ty * 4 + i;
            float4 v = make_float4(acc[i][0], acc[i][1], acc[i][2], acc[i][3]);
            *reinterpret_cast<float4*>(&C[m * N + bn * 64 + tx * 4]) = v;
        }
    } else {
        // scatter qkv: e in [0,3072); q/k/v split then [b,h,s,d]
#pragma unroll
        for (int i = 0; i < 4; i++) {
            int m = bm * 64 + ty * 4 + i;
            int b = m >> 11;
            int s = m & 2047;
#pragma unroll
            for (int j = 0; j < 4; j++) {
                int e = bn * 64 + tx * 4 + j;
                float val = acc[i][j];
                if (e < 1024) {
                    int h = e >> 6, d = e & 63;
                    g_Q[((b * HEADS + h) * S + s) * HD + d] = val;
                } else if (e < 2048) {
                    int e2 = e - 1024;
                    int h = e2 >> 6, d = e2 & 63;
                    g_K[((b * HEADS + h) * S + s) * HD + d] = val;
                } else {
                    int e2 = e - 2048;
                    int h = e2 >> 6, d = e2 & 63;
                    g_V[((b * HEADS + h) * S + s) * HD + d] = val;
                }
            }
        }
    }
}

// ---------------------------------------------------------------------------
// Fused flash attention (fp32). One block per (bh, q-tile of 64).
// Q tile [64,64] resident; loop over 32 K/V tiles of 64 rows; online softmax.
// 256 threads; thread (ty,tx) owns q-rows ty*4..+3 and dims/cols tx*4..+3.
// Dynamic smem = EXACTLY 48KB (no opt-in): Qs 64x64 | KtPs 64x64 | Vs 64x64.
// Kt XOR-swizzled: element (d,k) at d*64 + (k ^ d); buffer reused for P.
// ---------------------------------------------------------------------------
#define QS_OFF 0
#define KT_OFF 4096
#define VS_OFF 8192
#define ATTN_SMEM_FLOATS 12288   // 49152 bytes == 48KB

__global__ __launch_bounds__(256) void attn_kernel()
{
    extern __shared__ float sm[];
    float* Qs   = sm + QS_OFF;
    float* KtPs = sm + KT_OFF;   // Kt (swizzled), then P (plain)
    float* Vs   = sm + VS_OFF;

    const int tid = threadIdx.x;
    const int tx = tid & 15;
    const int ty = tid >> 4;
    const int qt = blockIdx.x;        // 0..31
    const int bh = blockIdx.y;        // 0..31
    const int b  = bh >> 4;
    const int h  = bh & 15;

    const float* Qg = g_Q + ((size_t)bh * S + qt * 64) * HD;
    const float* Kg = g_K + (size_t)bh * S * HD;
    const float* Vg = g_V + (size_t)bh * S * HD;

    // load Q tile (64x64), coalesced float4
    {
        int r0 = tid >> 4;            // 0..15
        int c  = (tid & 15) * 4;
#pragma unroll
        for (int p = 0; p < 4; p++) {
            int r = r0 + p * 16;
            *reinterpret_cast<float4*>(&Qs[r * 64 + c]) =
                *reinterpret_cast<const float4*>(&Qg[r * 64 + c]);
        }
    }

    float acc[4][4];
    float mrow[4], lrow[4];
#pragma unroll
    for (int i = 0; i < 4; i++) {
        mrow[i] = -CUDART_INF_F;
        lrow[i] = 0.f;
#pragma unroll
        for (int j = 0; j < 4; j++) acc[i][j] = 0.f;
    }

    for (int kt = 0; kt < S / 64; kt++) {
        __syncthreads();   // previous-iter P/V reads done; Q load done (kt=0)
        // load K tile transposed+swizzled, and V tile plain
        {
            int r0 = tid >> 4;
            int c  = (tid & 15) * 4;
#pragma unroll
            for (int p = 0; p < 4; p++) {
                int r = r0 + p * 16;
                float4 kv = *reinterpret_cast<const float4*>(&Kg[(kt * 64 + r) * 64 + c]);
                KtPs[(c + 0) * 64 + (r ^ (c + 0))] = kv.x;
                KtPs[(c + 1) * 64 + (r ^ (c + 1))] = kv.y;
                KtPs[(c + 2) * 64 + (r ^ (c + 2))] = kv.z;
                KtPs[(c + 3) * 64 + (r ^ (c + 3))] = kv.w;
                *reinterpret_cast<float4*>(&Vs[r * 64 + c]) =
                    *reinterpret_cast<const float4*>(&Vg[(kt * 64 + r) * 64 + c]);
            }
        }
        __syncthreads();

        // scores: s[i][j] = Q[qi,:] . K[kj,:]   (Kt swizzled: (d,k)->d*64+(k^d))
        float s[4][4];
#pragma unroll
        for (int i = 0; i < 4; i++)
#pragma unroll
            for (int j = 0; j < 4; j++) s[i][j] = 0.f;

#pragma unroll 8
        for (int d = 0; d < 64; d++) {
            float q0 = Qs[(ty * 4 + 0) * 64 + d];
            float q1 = Qs[(ty * 4 + 1) * 64 + d];
            float q2 = Qs[(ty * 4 + 2) * 64 + d];
            float q3 = Qs[(ty * 4 + 3) * 64 + d];
            const float* krow = &KtPs[d * 64];
            float k0 = krow[(tx * 4 + 0) ^ d];
            float k1 = krow[(tx * 4 + 1) ^ d];
            float k2 = krow[(tx * 4 + 2) ^ d];
            float k3 = krow[(tx * 4 + 3) ^ d];
            s[0][0] = fmaf(q0, k0, s[0][0]); s[0][1] = fmaf(q0, k1, s[0][1]);
            s[0][2] = fmaf(q0, k2, s[0][2]); s[0][3] = fmaf(q0, k3, s[0][3]);
            s[1][0] = fmaf(q1, k0, s[1][0]); s[1][1] = fmaf(q1, k1, s[1][1]);
            s[1][2] = fmaf(q1, k2, s[1][2]); s[1][3] = fmaf(q1, k3, s[1][3]);
            s[2][0] = fmaf(q2, k0, s[2][0]); s[2][1] = fmaf(q2, k1, s[2][1]);
            s[2][2] = fmaf(q2, k2, s[2][2]); s[2][3] = fmaf(q2, k3, s[2][3]);
            s[3][0] = fmaf(q3, k0, s[3][0]); s[3][1] = fmaf(q3, k1, s[3][1]);
            s[3][2] = fmaf(q3, k2, s[3][2]); s[3][3] = fmaf(q3, k3, s[3][3]);
        }

        __syncthreads();   // all Kt reads done before P overwrites the buffer

        // online softmax per q-row; 16 lanes (same ty) cooperate via shfl
#pragma unroll
        for (int i = 0; i < 4; i++) {
            float tm = -CUDART_INF_F;
#pragma unroll
            for (int j = 0; j < 4; j++) {
                s[i][j] *= SCALE;
                tm = fmaxf(tm, s[i][j]);
            }
#pragma unroll
            for (int off = 8; off >= 1; off >>= 1)
                tm = fmaxf(tm, __shfl_xor_sync(0xffffffffu, tm, off));
            float mnew = fmaxf(mrow[i], tm);
            float corr = __expf(mrow[i] - mnew);
            float rs = 0.f;
#pragma unroll
            for (int j = 0; j < 4; j++) {
                float p = __expf(s[i][j] - mnew);
                KtPs[(ty * 4 + i) * 64 + tx * 4 + j] = p;   // P, plain layout
                rs += p;
            }
#pragma unroll
            for (int off = 8; off >= 1; off >>= 1)
                rs += __shfl_xor_sync(0xffffffffu, rs, off);
            lrow[i] = lrow[i] * corr + rs;
            mrow[i] = mnew;
#pragma unroll
            for (int dd = 0; dd < 4; dd++) acc[i][dd] *= corr;
        }
        __syncthreads();

        // acc += P @ V
#pragma unroll 4
        for (int j = 0; j < 64; j++) {
            float4 v4 = *reinterpret_cast<const float4*>(&Vs[j * 64 + tx * 4]);
            float vr[4] = {v4.x, v4.y, v4.z, v4.w};
            float p0 = KtPs[(ty * 4 + 0) * 64 + j];
            float p1 = KtPs[(ty * 4 + 1) * 64 + j];
            float p2 = KtPs[(ty * 4 + 2) * 64 + j];
            float p3 = KtPs[(ty * 4 + 3) * 64 + j];
#pragma unroll
            for (int dd = 0; dd < 4; dd++) {
                acc[0][dd] = fmaf(p0, vr[dd], acc[0][dd]);
                acc[1][dd] = fmaf(p1, vr[dd], acc[1][dd]);
                acc[2][dd] = fmaf(p2, vr[dd], acc[2][dd]);
                acc[3][dd] = fmaf(p3, vr[dd], acc[3][dd]);
            }
        }
    }

    // write O in [b*s, h*64+d] layout
#pragma unroll
    for (int i = 0; i < 4; i++) {
        int srow = qt * 64 + ty * 4 + i;
        float inv = 1.f / lrow[i];
        float4 v = make_float4(acc[i][0] * inv, acc[i][1] * inv,
                               acc[i][2] * inv, acc[i][3] * inv);
        *reinterpret_cast<float4*>(
            &g_O[((size_t)(b * S + srow) * HID) + h * 64 + tx * 4]) = v;
    }
}

// ---------------------------------------------------------------------------
extern "C" void kernel_launch(void* const* d_in, const int* in_sizes, int n_in,
                              void* d_out, int out_size)
{
    // Positional per metadata (x, w_qkv, w_out), with size-based override.
    const float* x    = (const float*)d_in[0];
    const float* wqkv = (const float*)d_in[1];
    const float* wout = (const float*)d_in[2];
    for (int i = 0; i < n_in; i++) {
        if      (in_sizes[i] == 4194304) x    = (const float*)d_in[i];
        else if (in_sizes[i] == 3145728) wqkv = (const float*)d_in[i];
        else if (in_sizes[i] == 1048576) wout = (const float*)d_in[i];
    }
    float* out = (float*)d_out;

    // QKV projection: M=4096, N=3072, K=1024 -> scatter to g_Q/g_K/g_V
    gemm_kernel<1><<<dim3(3 * HID / 64, M_TOT / 64), 256>>>(x, wqkv, nullptr,
                                                            3 * HID, HID);
    // attention (48KB dynamic smem — no opt-in required)
    attn_kernel<<<dim3(S / 64, B * HEADS), 256,
                  ATTN_SMEM_FLOATS * sizeof(float)>>>();
    // out projection: M=4096, N=1024, K=1024 (A = g_O via device symbol)
    gemm_kernel<0><<<dim3(HID / 64, M_TOT / 64), 256>>>(nullptr, wout, out,
                                                        HID, HID);
}

// round 5
// speedup vs baseline: 1.2295x; 1.2295x over previous
#include <cuda_runtime.h>
#include <cuda_bf16.h>
#include <math_constants.h>
#include <cstdint>

// ---------------------------------------------------------------------------
// MHA: x[2,2048,1024] -> QKV proj -> 16-head attention -> out proj
// Round 5: projections via mma.sync bf16 (sm_80 baseline PTX - the harness
// PTX target is compute_103 WITHOUT 'a', so tcgen05 is unavailable).
// Precision: hi/lo split folded into extended-K GEMM:
//   A' = [Ahi | Ahi | Alo], B' = [Bhi | Blo | Bhi], K' = 3072
//   => AhiBhi + AhiBlo + AloBhi   (lo*lo dropped, ~1e-5 rel err)
// Attention stays fp32 flash kernel (proven, R3).
// ---------------------------------------------------------------------------

#define B_      2
#define S_      2048
#define HID     1024
#define HEADS   16
#define HD      64
#define M_TOT   (B_ * S_)          // 4096
#define SCALE   0.125f
#define K3      3072               // extended K

// fp32 scratch
__device__ float g_Q[B_ * HEADS * S_ * HD];
__device__ float g_K[B_ * HEADS * S_ * HD];
__device__ float g_V[B_ * HEADS * S_ * HD];
__device__ float g_O[M_TOT * HID];

// bf16 extended-K operands
__device__ __nv_bfloat16 g_Xe[M_TOT * K3];        // A' for QKV gemm
__device__ __nv_bfloat16 g_We[3 * HID * K3];      // B' for QKV gemm
__device__ __nv_bfloat16 g_Ue[HID * K3];          // B' for out gemm
__device__ __nv_bfloat16 g_Oe[M_TOT * K3];        // A' for out gemm

// ---------------------------------------------------------------------------
__device__ __forceinline__ uint32_t smem_u32(const void* p) {
    uint32_t a;
    asm("{ .reg .u64 t; cvta.to.shared.u64 t, %1; cvt.u32.u64 %0, t; }"
        : "=r"(a) : "l"(p));
    return a;
}
__device__ __forceinline__ void ldsm_x4(uint32_t* r, uint32_t addr) {
    asm volatile("ldmatrix.sync.aligned.m8n8.x4.shared.b16 {%0,%1,%2,%3}, [%4];"
        : "=r"(r[0]), "=r"(r[1]), "=r"(r[2]), "=r"(r[3]) : "r"(addr));
}
__device__ __forceinline__ void mma16816(float* d, const uint32_t* a,
                                         uint32_t b0, uint32_t b1) {
    asm volatile(
        "mma.sync.aligned.m16n8k16.row.col.f32.bf16.bf16.f32 "
        "{%0,%1,%2,%3}, {%4,%5,%6,%7}, {%8,%9}, {%0,%1,%2,%3};"
        : "+f"(d[0]), "+f"(d[1]), "+f"(d[2]), "+f"(d[3])
        : "r"(a[0]), "r"(a[1]), "r"(a[2]), "r"(a[3]), "r"(b0), "r"(b1));
}
__device__ __forceinline__ uint32_t sw(uint32_t off) {
    return off ^ ((off >> 3) & 0x70);   // SW128 xor swizzle, 128B rows
}

// ---------------------------------------------------------------------------
// fp32 -> extended-K bf16 converters.
// WHICH 0: x    -> g_Xe  (A-pattern [hi|hi|lo])
// WHICH 1: wqkv -> g_We  (B-pattern [hi|lo|hi])
// WHICH 2: wout -> g_Ue  (B-pattern)
// WHICH 3: g_O  -> g_Oe  (A-pattern)
// ---------------------------------------------------------------------------
template <int WHICH>
__global__ void convert_split(const float* __restrict__ src_in, int n)
{
    const float* src;
    __nv_bfloat16* dst;
    if      (WHICH == 0) { src = src_in; dst = g_Xe; }
    else if (WHICH == 1) { src = src_in; dst = g_We; }
    else if (WHICH == 2) { src = src_in; dst = g_Ue; }
    else                 { src = g_O;    dst = g_Oe; }

    for (int i = blockIdx.x * blockDim.x + threadIdx.x; i < n;
         i += gridDim.x * blockDim.x) {
        int m = i >> 10;            // row
        int k = i & 1023;           // col within original K=1024
        float xv = src[i];
        __nv_bfloat16 h = __float2bfloat16(xv);
        __nv_bfloat16 l = __float2bfloat16(xv - __bfloat162float(h));
        size_t base = (size_t)m * K3 + k;
        if (WHICH == 0 || WHICH == 3) {          // A-pattern
            dst[base]        = h;
            dst[base + 1024] = h;
            dst[base + 2048] = l;
        } else {                                  // B-pattern
            dst[base]        = h;
            dst[base + 1024] = l;
            dst[base + 2048] = h;
        }
    }
}

// ---------------------------------------------------------------------------
// mma.sync bf16 GEMM: C[m,n] = sum_k A'[m,k] * B'[n,k], K'=3072.
// CTA tile 128x128, 8 warps (2 along M x 4 along N), warp tile 64x32.
// K-chunk 64, register-staged global loads, XOR-swizzled smem, ldmatrix.
// MODE 0: A'=g_Xe, B'=g_We (N=3072), epilogue scatters to g_Q/g_K/g_V.
// MODE 1: A'=g_Oe, B'=g_Ue (N=1024), epilogue writes Cout row-major.
// ---------------------------------------------------------------------------
template <int MODE>
__global__ __launch_bounds__(256) void mma_gemm(float* __restrict__ Cout)
{
    __shared__ __align__(128) __nv_bfloat16 As[128 * 64];
    __shared__ __align__(128) __nv_bfloat16 Bs[128 * 64];

    const int tid = threadIdx.x;
    const int wid = tid >> 5;
    const int lid = tid & 31;
    const int bn = blockIdx.x;
    const int bm = blockIdx.y;
    const int wm = wid & 1;          // 0..1 -> M offset wm*64
    const int wn = wid >> 1;         // 0..3 -> N offset wn*32

    const __nv_bfloat16* Ag = (MODE == 0) ? g_Xe : g_Oe;
    const __nv_bfloat16* Bg = (MODE == 0) ? g_We : g_Ue;

    const uint32_t sA = smem_u32(As);
    const uint32_t sB = smem_u32(Bs);

    float acc[4][4][4];
#pragma unroll
    for (int a = 0; a < 4; a++)
#pragma unroll
        for (int b = 0; b < 4; b++)
#pragma unroll
            for (int c = 0; c < 4; c++) acc[a][b][c] = 0.f;

    const int lrow = lid & 15;       // ldmatrix lane row
    const int lkb  = lid >> 4;       // ldmatrix lane k-block

    for (int kt = 0; kt < K3 / 64; kt++) {
        // ---- stage tile loads in registers (overlaps with prior compute) ----
        uint4 av[4], bv[4];
#pragma unroll
        for (int p = 0; p < 4; p++) {
            int idx = tid + p * 256;        // 0..1023
            int r = idx >> 3, j = idx & 7;
            av[p] = *reinterpret_cast<const uint4*>(
                Ag + (size_t)(bm * 128 + r) * K3 + kt * 64 + j * 8);
            bv[p] = *reinterpret_cast<const uint4*>(
                Bg + (size_t)(bn * 128 + r) * K3 + kt * 64 + j * 8);
        }
        __syncthreads();            // previous compute done
#pragma unroll
        for (int p = 0; p < 4; p++) {
            int idx = tid + p * 256;
            int r = idx >> 3, j = idx & 7;
            uint32_t o = sw((uint32_t)(r * 128 + j * 16));
            *reinterpret_cast<uint4*>(reinterpret_cast<char*>(As) + o) = av[p];
            *reinterpret_cast<uint4*>(reinterpret_cast<char*>(Bs) + o) = bv[p];
        }
        __syncthreads();

        // ---- 4 k16 steps ----
#pragma unroll
        for (int ks = 0; ks < 4; ks++) {
            uint32_t afr[4][4], bfr[2][4];
#pragma unroll
            for (int mi = 0; mi < 4; mi++) {
                uint32_t o = (uint32_t)((wm * 64 + mi * 16 + lrow) * 128 +
                                        ks * 32 + lkb * 16);
                ldsm_x4(afr[mi], sA + sw(o));
            }
#pragma unroll
            for (int nb = 0; nb < 2; nb++) {
                uint32_t o = (uint32_t)((wn * 32 + nb * 16 + lrow) * 128 +
                                        ks * 32 + lkb * 16);
                ldsm_x4(bfr[nb], sB + sw(o));
            }
            // bfr[nb]: r0=(n0-7,k0-7) r1=(n8-15,k0-7) r2=(n0-7,k8-15) r3=(n8-15,k8-15)
#pragma unroll
            for (int mi = 0; mi < 4; mi++)
#pragma unroll
                for (int ni = 0; ni < 4; ni++)
                    mma16816(acc[mi][ni], afr[mi],
                             bfr[ni >> 1][ni & 1], bfr[ni >> 1][(ni & 1) + 2]);
        }
    }

    // ---- epilogue ----
    // acc frag element map: c0:(tg,tc) c1:(tg,tc+1) c2:(tg+8,tc) c3:(tg+8,tc+1)
    const int tg = lid >> 2;
    const int tc = (lid & 3) * 2;

    if (MODE == 1) {
#pragma unroll
        for (int mi = 0; mi < 4; mi++)
#pragma unroll
            for (int ni = 0; ni < 4; ni++) {
                int m0 = bm * 128 + wm * 64 + mi * 16 + tg;
                int n0 = bn * 128 + wn * 32 + ni * 8 + tc;
                float2 v0 = make_float2(acc[mi][ni][0], acc[mi][ni][1]);
                float2 v1 = make_float2(acc[mi][ni][2], acc[mi][ni][3]);
                *reinterpret_cast<float2*>(&Cout[(size_t)m0 * HID + n0]) = v0;
                *reinterpret_cast<float2*>(&Cout[(size_t)(m0 + 8) * HID + n0]) = v1;
            }
    } else {
#pragma unroll
        for (int mi = 0; mi < 4; mi++)
#pragma unroll
            for (int ni = 0; ni < 4; ni++) {
#pragma unroll
                for (int q = 0; q < 4; q++) {
                    int m = bm * 128 + wm * 64 + mi * 16 + tg + (q >> 1) * 8;
                    int e = bn * 128 + wn * 32 + ni * 8 + tc + (q & 1);
                    float val = acc[mi][ni][q];
                    int b = m >> 11, s = m & 2047;
                    int region = e >> 10;
                    int e2 = e & 1023;
                    int h = e2 >> 6, d = e2 & 63;
                    size_t off = ((size_t)(b * HEADS + h) * S_ + s) * HD + d;
                    if      (region == 0) g_Q[off] = val;
                    else if (region == 1) g_K[off] = val;
                    else                  g_V[off] = val;
                }
            }
    }
}

// ---------------------------------------------------------------------------
// Fused flash attention (fp32) — unchanged from Round 3 (proven correct).
// ---------------------------------------------------------------------------
#define QS_OFF 0
#define KT_OFF 4096
#define VS_OFF 8192
#define ATTN_SMEM_FLOATS 12288   // 48KB

__global__ __launch_bounds__(256) void attn_kernel()
{
    extern __shared__ float sm[];
    float* Qs   = sm + QS_OFF;
    float* KtPs = sm + KT_OFF;
    float* Vs   = sm + VS_OFF;

    const int tid = threadIdx.x;
    const int tx = tid & 15;
    const int ty = tid >> 4;
    const int qt = blockIdx.x;
    const int bh = blockIdx.y;
    const int b  = bh >> 4;
    const int h  = bh & 15;

    const float* Qg = g_Q + ((size_t)bh * S_ + qt * 64) * HD;
    const float* Kg = g_K + (size_t)bh * S_ * HD;
    const float* Vg = g_V + (size_t)bh * S_ * HD;

    {
        int r0 = tid >> 4;
        int c  = (tid & 15) * 4;
#pragma unroll
        for (int p = 0; p < 4; p++) {
            int r = r0 + p * 16;
            *reinterpret_cast<float4*>(&Qs[r * 64 + c]) =
                *reinterpret_cast<const float4*>(&Qg[r * 64 + c]);
        }
    }

    float acc[4][4];
    float mrow[4], lrow[4];
#pragma unroll
    for (int i = 0; i < 4; i++) {
        mrow[i] = -CUDART_INF_F;
        lrow[i] = 0.f;
#pragma unroll
        for (int j = 0; j < 4; j++) acc[i][j] = 0.f;
    }

    for (int kt = 0; kt < S_ / 64; kt++) {
        __syncthreads();
        {
            int r0 = tid >> 4;
            int c  = (tid & 15) * 4;
#pragma unroll
            for (int p = 0; p < 4; p++) {
                int r = r0 + p * 16;
                float4 kv = *reinterpret_cast<const float4*>(&Kg[(kt * 64 + r) * 64 + c]);
                KtPs[(c + 0) * 64 + (r ^ (c + 0))] = kv.x;
                KtPs[(c + 1) * 64 + (r ^ (c + 1))] = kv.y;
                KtPs[(c + 2) * 64 + (r ^ (c + 2))] = kv.z;
                KtPs[(c + 3) * 64 + (r ^ (c + 3))] = kv.w;
                *reinterpret_cast<float4*>(&Vs[r * 64 + c]) =
                    *reinterpret_cast<const float4*>(&Vg[(kt * 64 + r) * 64 + c]);
            }
        }
        __syncthreads();

        float s[4][4];
#pragma unroll
        for (int i = 0; i < 4; i++)
#pragma unroll
            for (int j = 0; j < 4; j++) s[i][j] = 0.f;

#pragma unroll 8
        for (int d = 0; d < 64; d++) {
            float q0 = Qs[(ty * 4 + 0) * 64 + d];
            float q1 = Qs[(ty * 4 + 1) * 64 + d];
            float q2 = Qs[(ty * 4 + 2) * 64 + d];
            float q3 = Qs[(ty * 4 + 3) * 64 + d];
            const float* krow = &KtPs[d * 64];
            float k0 = krow[(tx * 4 + 0) ^ d];
            float k1 = krow[(tx * 4 + 1) ^ d];
            float k2 = krow[(tx * 4 + 2) ^ d];
            float k3 = krow[(tx * 4 + 3) ^ d];
            s[0][0] = fmaf(q0, k0, s[0][0]); s[0][1] = fmaf(q0, k1, s[0][1]);
            s[0][2] = fmaf(q0, k2, s[0][2]); s[0][3] = fmaf(q0, k3, s[0][3]);
            s[1][0] = fmaf(q1, k0, s[1][0]); s[1][1] = fmaf(q1, k1, s[1][1]);
            s[1][2] = fmaf(q1, k2, s[1][2]); s[1][3] = fmaf(q1, k3, s[1][3]);
            s[2][0] = fmaf(q2, k0, s[2][0]); s[2][1] = fmaf(q2, k1, s[2][1]);
            s[2][2] = fmaf(q2, k2, s[2][2]); s[2][3] = fmaf(q2, k3, s[2][3]);
            s[3][0] = fmaf(q3, k0, s[3][0]); s[3][1] = fmaf(q3, k1, s[3][1]);
            s[3][2] = fmaf(q3, k2, s[3][2]); s[3][3] = fmaf(q3, k3, s[3][3]);
        }

        __syncthreads();

#pragma unroll
        for (int i = 0; i < 4; i++) {
            float tm = -CUDART_INF_F;
#pragma unroll
            for (int j = 0; j < 4; j++) {
                s[i][j] *= SCALE;
                tm = fmaxf(tm, s[i][j]);
            }
#pragma unroll
            for (int off = 8; off >= 1; off >>= 1)
                tm = fmaxf(tm, __shfl_xor_sync(0xffffffffu, tm, off));
            float mnew = fmaxf(mrow[i], tm);
            float corr = __expf(mrow[i] - mnew);
            float rs = 0.f;
#pragma unroll
            for (int j = 0; j < 4; j++) {
                float p = __expf(s[i][j] - mnew);
                KtPs[(ty * 4 + i) * 64 + tx * 4 + j] = p;
                rs += p;
            }
#pragma unroll
            for (int off = 8; off >= 1; off >>= 1)
                rs += __shfl_xor_sync(0xffffffffu, rs, off);
            lrow[i] = lrow[i] * corr + rs;
            mrow[i] = mnew;
#pragma unroll
            for (int dd = 0; dd < 4; dd++) acc[i][dd] *= corr;
        }
        __syncthreads();

#pragma unroll 4
        for (int j = 0; j < 64; j++) {
            float4 v4 = *reinterpret_cast<const float4*>(&Vs[j * 64 + tx * 4]);
            float vr[4] = {v4.x, v4.y, v4.z, v4.w};
            float p0 = KtPs[(ty * 4 + 0) * 64 + j];
            float p1 = KtPs[(ty * 4 + 1) * 64 + j];
            float p2 = KtPs[(ty * 4 + 2) * 64 + j];
            float p3 = KtPs[(ty * 4 + 3) * 64 + j];
#pragma unroll
            for (int dd = 0; dd < 4; dd++) {
                acc[0][dd] = fmaf(p0, vr[dd], acc[0][dd]);
                acc[1][dd] = fmaf(p1, vr[dd], acc[1][dd]);
                acc[2][dd] = fmaf(p2, vr[dd], acc[2][dd]);
                acc[3][dd] = fmaf(p3, vr[dd], acc[3][dd]);
            }
        }
    }

#pragma unroll
    for (int i = 0; i < 4; i++) {
        int srow = qt * 64 + ty * 4 + i;
        float inv = 1.f / lrow[i];
        float4 v = make_float4(acc[i][0] * inv, acc[i][1] * inv,
                               acc[i][2] * inv, acc[i][3] * inv);
        *reinterpret_cast<float4*>(
            &g_O[((size_t)(b * S_ + srow) * HID) + h * 64 + tx * 4]) = v;
    }
}

// ---------------------------------------------------------------------------
extern "C" void kernel_launch(void* const* d_in, const int* in_sizes, int n_in,
                              void* d_out, int out_size)
{
    const float* x    = (const float*)d_in[0];
    const float* wqkv = (const float*)d_in[1];
    const float* wout = (const float*)d_in[2];
    for (int i = 0; i < n_in; i++) {
        if      (in_sizes[i] == 4194304) x    = (const float*)d_in[i];
        else if (in_sizes[i] == 3145728) wqkv = (const float*)d_in[i];
        else if (in_sizes[i] == 1048576) wout = (const float*)d_in[i];
    }
    float* out = (float*)d_out;

    // build extended-K bf16 operands
    convert_split<0><<<1024, 256>>>(x,    M_TOT * HID);
    convert_split<1><<<1024, 256>>>(wqkv, 3 * HID * HID);
    convert_split<2><<<1024, 256>>>(wout, HID * HID);

    // QKV projection (tensor cores), scatter to g_Q/g_K/g_V
    mma_gemm<0><<<dim3(3 * HID / 128, M_TOT / 128), 256>>>(nullptr);

    // attention (fp32, 48KB dynamic smem)
    attn_kernel<<<dim3(S_ / 64, B_ * HEADS), 256,
                  ATTN_SMEM_FLOATS * sizeof(float)>>>();

    // out projection (tensor cores) -> d_out
    convert_split<3><<<1024, 256>>>(nullptr, M_TOT * HID);
    mma_gemm<1><<<dim3(HID / 128, M_TOT / 128), 256>>>(out);
}

// round 6
// speedup vs baseline: 1.9961x; 1.6235x over previous
#include <cuda_runtime.h>
#include <cuda_bf16.h>
#include <math_constants.h>
#include <cstdint>

// ---------------------------------------------------------------------------
// MHA Round 6: projections via mma.sync bf16 extended-K (R5, proven) and
// attention ALSO via mma.sync bf16 with 3-term hi/lo compensation.
// ---------------------------------------------------------------------------

#define B_      2
#define S_      2048
#define HID     1024
#define HEADS   16
#define HD      64
#define M_TOT   (B_ * S_)
#define SCALE   0.125f
#define K3      3072

// fp32 scratch
__device__ float g_Q[B_ * HEADS * S_ * HD];
__device__ float g_K[B_ * HEADS * S_ * HD];
__device__ float g_V[B_ * HEADS * S_ * HD];
__device__ float g_O[M_TOT * HID];

// bf16 extended-K GEMM operands
__device__ __nv_bfloat16 g_Xe[M_TOT * K3];
__device__ __nv_bfloat16 g_We[3 * HID * K3];
__device__ __nv_bfloat16 g_Ue[HID * K3];
__device__ __nv_bfloat16 g_Oe[M_TOT * K3];

// bf16 split attention operands
__device__ __nv_bfloat16 g_Qh[B_ * HEADS * S_ * HD];   // [bh][s][d] (scale folded)
__device__ __nv_bfloat16 g_Ql[B_ * HEADS * S_ * HD];
__device__ __nv_bfloat16 g_Kh[B_ * HEADS * S_ * HD];   // [bh][s][d]
__device__ __nv_bfloat16 g_Kl[B_ * HEADS * S_ * HD];
__device__ __nv_bfloat16 g_Vth[B_ * HEADS * HD * S_];  // [bh][d][s] transposed
__device__ __nv_bfloat16 g_Vtl[B_ * HEADS * HD * S_];

// ---------------------------------------------------------------------------
__device__ __forceinline__ uint32_t smem_u32(const void* p) {
    uint32_t a;
    asm("{ .reg .u64 t; cvta.to.shared.u64 t, %1; cvt.u32.u64 %0, t; }"
        : "=r"(a) : "l"(p));
    return a;
}
__device__ __forceinline__ void ldsm_x4(uint32_t* r, uint32_t addr) {
    asm volatile("ldmatrix.sync.aligned.m8n8.x4.shared.b16 {%0,%1,%2,%3}, [%4];"
        : "=r"(r[0]), "=r"(r[1]), "=r"(r[2]), "=r"(r[3]) : "r"(addr));
}
__device__ __forceinline__ void mma16816(float* d, const uint32_t* a,
                                         uint32_t b0, uint32_t b1) {
    asm volatile(
        "mma.sync.aligned.m16n8k16.row.col.f32.bf16.bf16.f32 "
        "{%0,%1,%2,%3}, {%4,%5,%6,%7}, {%8,%9}, {%0,%1,%2,%3};"
        : "+f"(d[0]), "+f"(d[1]), "+f"(d[2]), "+f"(d[3])
        : "r"(a[0]), "r"(a[1]), "r"(a[2]), "r"(a[3]), "r"(b0), "r"(b1));
}
__device__ __forceinline__ uint32_t sw(uint32_t off) {
    return off ^ ((off >> 3) & 0x70);
}
__device__ __forceinline__ uint32_t pack_bf16(float lo, float hi) {
    __nv_bfloat162 t = __floats2bfloat162_rn(lo, hi);   // .x = low half
    return *reinterpret_cast<uint32_t*>(&t);
}

// ---------------------------------------------------------------------------
// extended-K converters (unchanged from R5)
// ---------------------------------------------------------------------------
template <int WHICH>
__global__ void convert_split(const float* __restrict__ src_in, int n)
{
    const float* src;
    __nv_bfloat16* dst;
    if      (WHICH == 0) { src = src_in; dst = g_Xe; }
    else if (WHICH == 1) { src = src_in; dst = g_We; }
    else if (WHICH == 2) { src = src_in; dst = g_Ue; }
    else                 { src = g_O;    dst = g_Oe; }

    for (int i = blockIdx.x * blockDim.x + threadIdx.x; i < n;
         i += gridDim.x * blockDim.x) {
        int m = i >> 10;
        int k = i & 1023;
        float xv = src[i];
        __nv_bfloat16 h = __float2bfloat16(xv);
        __nv_bfloat16 l = __float2bfloat16(xv - __bfloat162float(h));
        size_t base = (size_t)m * K3 + k;
        if (WHICH == 0 || WHICH == 3) {
            dst[base] = h; dst[base + 1024] = h; dst[base + 2048] = l;
        } else {
            dst[base] = h; dst[base + 1024] = l; dst[base + 2048] = h;
        }
    }
}

// ---------------------------------------------------------------------------
// prep: g_Q/g_K/g_V fp32 -> split bf16 attention operands
// ---------------------------------------------------------------------------
__global__ void prep_attn()
{
    const int n = B_ * HEADS * S_ * HD;
    for (int i = blockIdx.x * blockDim.x + threadIdx.x; i < n;
         i += gridDim.x * blockDim.x) {
        float q = g_Q[i] * SCALE;
        __nv_bfloat16 qh = __float2bfloat16(q);
        g_Qh[i] = qh;
        g_Ql[i] = __float2bfloat16(q - __bfloat162float(qh));

        float k = g_K[i];
        __nv_bfloat16 kh = __float2bfloat16(k);
        g_Kh[i] = kh;
        g_Kl[i] = __float2bfloat16(k - __bfloat162float(kh));

        float v = g_V[i];
        __nv_bfloat16 vh = __float2bfloat16(v);
        int bh = i >> 17;              // / (2048*64)
        int s  = (i >> 6) & 2047;
        int d  = i & 63;
        size_t t = ((size_t)bh * HD + d) * S_ + s;
        g_Vth[t] = vh;
        g_Vtl[t] = __float2bfloat16(v - __bfloat162float(vh));
    }
}

// ---------------------------------------------------------------------------
// mma.sync GEMM (unchanged from R5, proven)
// ---------------------------------------------------------------------------
template <int MODE>
__global__ __launch_bounds__(256) void mma_gemm(float* __restrict__ Cout)
{
    __shared__ __align__(128) __nv_bfloat16 As[128 * 64];
    __shared__ __align__(128) __nv_bfloat16 Bs[128 * 64];

    const int tid = threadIdx.x;
    const int wid = tid >> 5;
    const int lid = tid & 31;
    const int bn = blockIdx.x;
    const int bm = blockIdx.y;
    const int wm = wid & 1;
    const int wn = wid >> 1;

    const __nv_bfloat16* Ag = (MODE == 0) ? g_Xe : g_Oe;
    const __nv_bfloat16* Bg = (MODE == 0) ? g_We : g_Ue;

    const uint32_t sA = smem_u32(As);
    const uint32_t sB = smem_u32(Bs);

    float acc[4][4][4];
#pragma unroll
    for (int a = 0; a < 4; a++)
#pragma unroll
        for (int b = 0; b < 4; b++)
#pragma unroll
            for (int c = 0; c < 4; c++) acc[a][b][c] = 0.f;

    const int lrow = lid & 15;
    const int lkb  = lid >> 4;

    for (int kt = 0; kt < K3 / 64; kt++) {
        uint4 av[4], bv[4];
#pragma unroll
        for (int p = 0; p < 4; p++) {
            int idx = tid + p * 256;
            int r = idx >> 3, j = idx & 7;
            av[p] = *reinterpret_cast<const uint4*>(
                Ag + (size_t)(bm * 128 + r) * K3 + kt * 64 + j * 8);
            bv[p] = *reinterpret_cast<const uint4*>(
                Bg + (size_t)(bn * 128 + r) * K3 + kt * 64 + j * 8);
        }
        __syncthreads();
#pragma unroll
        for (int p = 0; p < 4; p++) {
            int idx = tid + p * 256;
            int r = idx >> 3, j = idx & 7;
            uint32_t o = sw((uint32_t)(r * 128 + j * 16));
            *reinterpret_cast<uint4*>(reinterpret_cast<char*>(As) + o) = av[p];
            *reinterpret_cast<uint4*>(reinterpret_cast<char*>(Bs) + o) = bv[p];
        }
        __syncthreads();

#pragma unroll
        for (int ks = 0; ks < 4; ks++) {
            uint32_t afr[4][4], bfr[2][4];
#pragma unroll
            for (int mi = 0; mi < 4; mi++) {
                uint32_t o = (uint32_t)((wm * 64 + mi * 16 + lrow) * 128 +
                                        ks * 32 + lkb * 16);
                ldsm_x4(afr[mi], sA + sw(o));
            }
#pragma unroll
            for (int nb = 0; nb < 2; nb++) {
                uint32_t o = (uint32_t)((wn * 32 + nb * 16 + lrow) * 128 +
                                        ks * 32 + lkb * 16);
                ldsm_x4(bfr[nb], sB + sw(o));
            }
#pragma unroll
            for (int mi = 0; mi < 4; mi++)
#pragma unroll
                for (int ni = 0; ni < 4; ni++)
                    mma16816(acc[mi][ni], afr[mi],
                             bfr[ni >> 1][ni & 1], bfr[ni >> 1][(ni & 1) + 2]);
        }
    }

    const int tg = lid >> 2;
    const int tc = (lid & 3) * 2;

    if (MODE == 1) {
#pragma unroll
        for (int mi = 0; mi < 4; mi++)
#pragma unroll
            for (int ni = 0; ni < 4; ni++) {
                int m0 = bm * 128 + wm * 64 + mi * 16 + tg;
                int n0 = bn * 128 + wn * 32 + ni * 8 + tc;
                float2 v0 = make_float2(acc[mi][ni][0], acc[mi][ni][1]);
                float2 v1 = make_float2(acc[mi][ni][2], acc[mi][ni][3]);
                *reinterpret_cast<float2*>(&Cout[(size_t)m0 * HID + n0]) = v0;
                *reinterpret_cast<float2*>(&Cout[(size_t)(m0 + 8) * HID + n0]) = v1;
            }
    } else {
#pragma unroll
        for (int mi = 0; mi < 4; mi++)
#pragma unroll
            for (int ni = 0; ni < 4; ni++)
#pragma unroll
                for (int q = 0; q < 4; q++) {
                    int m = bm * 128 + wm * 64 + mi * 16 + tg + (q >> 1) * 8;
                    int e = bn * 128 + wn * 32 + ni * 8 + tc + (q & 1);
                    float val = acc[mi][ni][q];
                    int b = m >> 11, s = m & 2047;
                    int region = e >> 10;
                    int e2 = e & 1023;
                    int h = e2 >> 6, d = e2 & 63;
                    size_t off = ((size_t)(b * HEADS + h) * S_ + s) * HD + d;
                    if      (region == 0) g_Q[off] = val;
                    else if (region == 1) g_K[off] = val;
                    else                  g_V[off] = val;
                }
    }
}

// ---------------------------------------------------------------------------
// Tensor-core flash attention, 3-term hi/lo compensated bf16.
// Block: 128 threads (4 warps). Block tile: 64 q-rows; warp w owns rows
// w*16..+15. K-loop over 32 key tiles of 64. Smem: 6 x (64x64 bf16) = 48KB.
// ---------------------------------------------------------------------------
__device__ __forceinline__ void load_tile64(__nv_bfloat16* s,
                                            const __nv_bfloat16* g,
                                            int gstride, int tid)
{
#pragma unroll
    for (int p = 0; p < 4; p++) {
        int idx = tid + p * 128;          // 0..511
        int r = idx >> 3, j = idx & 7;
        uint4 v = *reinterpret_cast<const uint4*>(g + (size_t)r * gstride + j * 8);
        *reinterpret_cast<uint4*>(
            reinterpret_cast<char*>(s) + sw((uint32_t)(r * 128 + j * 16))) = v;
    }
}

__global__ __launch_bounds__(128) void attn_mma()
{
    __shared__ __align__(128) __nv_bfloat16 sQh[4096], sQl[4096];
    __shared__ __align__(128) __nv_bfloat16 sKh[4096], sKl[4096];
    __shared__ __align__(128) __nv_bfloat16 sVh[4096], sVl[4096];

    const int tid = threadIdx.x;
    const int wid = tid >> 5;
    const int lid = tid & 31;
    const int qt = blockIdx.x;
    const int bh = blockIdx.y;
    const int b  = bh >> 4;
    const int h  = bh & 15;

    const int lrow = lid & 15;
    const int lkb  = lid >> 4;
    const int tg   = lid >> 2;
    const int tc   = (lid & 3) * 2;

    const size_t qoff = ((size_t)bh * S_ + qt * 64) * HD;
    load_tile64(sQh, g_Qh + qoff, HD, tid);
    load_tile64(sQl, g_Ql + qoff, HD, tid);
    __syncthreads();

    // Q fragments (resident): 4 k16 steps x 4 regs, hi & lo
    uint32_t qfh[4][4], qfl[4][4];
    const uint32_t aQh = smem_u32(sQh), aQl = smem_u32(sQl);
#pragma unroll
    for (int ks = 0; ks < 4; ks++) {
        uint32_t o = (uint32_t)((wid * 16 + lrow) * 128 + ks * 32 + lkb * 16);
        ldsm_x4(qfh[ks], aQh + sw(o));
        ldsm_x4(qfl[ks], aQl + sw(o));
    }

    float oacc[8][4];
#pragma unroll
    for (int t = 0; t < 8; t++)
#pragma unroll
        for (int c = 0; c < 4; c++) oacc[t][c] = 0.f;
    float m0 = -CUDART_INF_F, m1 = -CUDART_INF_F;
    float l0 = 0.f, l1 = 0.f;

    const uint32_t aKh = smem_u32(sKh), aKl = smem_u32(sKl);
    const uint32_t aVh = smem_u32(sVh), aVl = smem_u32(sVl);

    for (int kt = 0; kt < S_ / 64; kt++) {
        __syncthreads();
        {
            const size_t koff = ((size_t)bh * S_ + kt * 64) * HD;
            load_tile64(sKh, g_Kh + koff, HD, tid);
            load_tile64(sKl, g_Kl + koff, HD, tid);
            const size_t voff = (size_t)bh * HD * S_ + kt * 64;
            load_tile64(sVh, g_Vth + voff, S_, tid);
            load_tile64(sVl, g_Vtl + voff, S_, tid);
        }
        __syncthreads();

        // ---- S = Q K^T (scale pre-folded), 3-term ----
        float sacc[8][4];
#pragma unroll
        for (int t = 0; t < 8; t++)
#pragma unroll
            for (int c = 0; c < 4; c++) sacc[t][c] = 0.f;

#pragma unroll
        for (int ks = 0; ks < 4; ks++) {
            uint32_t kbh[4][4], kbl[4][4];
#pragma unroll
            for (int nb = 0; nb < 4; nb++) {
                uint32_t o = (uint32_t)((nb * 16 + lrow) * 128 + ks * 32 + lkb * 16);
                ldsm_x4(kbh[nb], aKh + sw(o));
                ldsm_x4(kbl[nb], aKl + sw(o));
            }
#pragma unroll
            for (int nt = 0; nt < 8; nt++) {
                uint32_t bh0 = kbh[nt >> 1][nt & 1], bh1 = kbh[nt >> 1][(nt & 1) + 2];
                uint32_t bl0 = kbl[nt >> 1][nt & 1], bl1 = kbl[nt >> 1][(nt & 1) + 2];
                mma16816(sacc[nt], qfh[ks], bh0, bh1);
                mma16816(sacc[nt], qfh[ks], bl0, bl1);
                mma16816(sacc[nt], qfl[ks], bh0, bh1);
            }
        }

        // ---- online softmax (rows tg and tg+8) ----
        float rm0 = -CUDART_INF_F, rm1 = -CUDART_INF_F;
#pragma unroll
        for (int t = 0; t < 8; t++) {
            rm0 = fmaxf(rm0, fmaxf(sacc[t][0], sacc[t][1]));
            rm1 = fmaxf(rm1, fmaxf(sacc[t][2], sacc[t][3]));
        }
        rm0 = fmaxf(rm0, __shfl_xor_sync(0xffffffffu, rm0, 1));
        rm0 = fmaxf(rm0, __shfl_xor_sync(0xffffffffu, rm0, 2));
        rm1 = fmaxf(rm1, __shfl_xor_sync(0xffffffffu, rm1, 1));
        rm1 = fmaxf(rm1, __shfl_xor_sync(0xffffffffu, rm1, 2));

        float mn0 = fmaxf(m0, rm0), mn1 = fmaxf(m1, rm1);
        float cr0 = __expf(m0 - mn0), cr1 = __expf(m1 - mn1);
        m0 = mn0; m1 = mn1;

        float rs0 = 0.f, rs1 = 0.f;
#pragma unroll
        for (int t = 0; t < 8; t++) {
            sacc[t][0] = __expf(sacc[t][0] - mn0);
            sacc[t][1] = __expf(sacc[t][1] - mn0);
            sacc[t][2] = __expf(sacc[t][2] - mn1);
            sacc[t][3] = __expf(sacc[t][3] - mn1);
            rs0 += sacc[t][0] + sacc[t][1];
            rs1 += sacc[t][2] + sacc[t][3];
        }
        rs0 += __shfl_xor_sync(0xffffffffu, rs0, 1);
        rs0 += __shfl_xor_sync(0xffffffffu, rs0, 2);
        rs1 += __shfl_xor_sync(0xffffffffu, rs1, 1);
        rs1 += __shfl_xor_sync(0xffffffffu, rs1, 2);
        l0 = l0 * cr0 + rs0;
        l1 = l1 * cr1 + rs1;

#pragma unroll
        for (int t = 0; t < 8; t++) {
            oacc[t][0] *= cr0; oacc[t][1] *= cr0;
            oacc[t][2] *= cr1; oacc[t][3] *= cr1;
        }

        // ---- pack P fragments (hi/lo) from S accumulators ----
        uint32_t pah[4][4], pal[4][4];
#pragma unroll
        for (int ks = 0; ks < 4; ks++) {
            const int t0 = 2 * ks, t1 = 2 * ks + 1;
            float ph[8], pl[8];
            const float pv[8] = {sacc[t0][0], sacc[t0][1], sacc[t0][2], sacc[t0][3],
                                 sacc[t1][0], sacc[t1][1], sacc[t1][2], sacc[t1][3]};
#pragma unroll
            for (int e = 0; e < 8; e++) {
                __nv_bfloat16 hb = __float2bfloat16(pv[e]);
                ph[e] = __bfloat162float(hb);
                pl[e] = pv[e] - ph[e];
            }
            pah[ks][0] = pack_bf16(ph[0], ph[1]);
            pah[ks][1] = pack_bf16(ph[2], ph[3]);
            pah[ks][2] = pack_bf16(ph[4], ph[5]);
            pah[ks][3] = pack_bf16(ph[6], ph[7]);
            pal[ks][0] = pack_bf16(pl[0], pl[1]);
            pal[ks][1] = pack_bf16(pl[2], pl[3]);
            pal[ks][2] = pack_bf16(pl[4], pl[5]);
            pal[ks][3] = pack_bf16(pl[6], pl[7]);
        }

        // ---- O += P V, 3-term ----
#pragma unroll
        for (int ks = 0; ks < 4; ks++) {
            uint32_t vbh[4][4], vbl[4][4];
#pragma unroll
            for (int nb = 0; nb < 4; nb++) {
                uint32_t o = (uint32_t)((nb * 16 + lrow) * 128 + ks * 32 + lkb * 16);
                ldsm_x4(vbh[nb], aVh + sw(o));
                ldsm_x4(vbl[nb], aVl + sw(o));
            }
#pragma unroll
            for (int nt = 0; nt < 8; nt++) {
                uint32_t bh0 = vbh[nt >> 1][nt & 1], bh1 = vbh[nt >> 1][(nt & 1) + 2];
                uint32_t bl0 = vbl[nt >> 1][nt & 1], bl1 = vbl[nt >> 1][(nt & 1) + 2];
                mma16816(oacc[nt], pah[ks], bh0, bh1);
                mma16816(oacc[nt], pah[ks], bl0, bl1);
                mma16816(oacc[nt], pal[ks], bh0, bh1);
            }
        }
    }

    // ---- write O ----
    const float inv0 = 1.f / l0, inv1 = 1.f / l1;
    const int r0 = qt * 64 + wid * 16 + tg;
#pragma unroll
    for (int nt = 0; nt < 8; nt++) {
        int col = h * 64 + nt * 8 + tc;
        *reinterpret_cast<float2*>(&g_O[(size_t)(b * S_ + r0) * HID + col]) =
            make_float2(oacc[nt][0] * inv0, oacc[nt][1] * inv0);
        *reinterpret_cast<float2*>(&g_O[(size_t)(b * S_ + r0 + 8) * HID + col]) =
            make_float2(oacc[nt][2] * inv1, oacc[nt][3] * inv1);
    }
}

// ---------------------------------------------------------------------------
extern "C" void kernel_launch(void* const* d_in, const int* in_sizes, int n_in,
                              void* d_out, int out_size)
{
    const float* x    = (const float*)d_in[0];
    const float* wqkv = (const float*)d_in[1];
    const float* wout = (const float*)d_in[2];
    for (int i = 0; i < n_in; i++) {
        if      (in_sizes[i] == 4194304) x    = (const float*)d_in[i];
        else if (in_sizes[i] == 3145728) wqkv = (const float*)d_in[i];
        else if (in_sizes[i] == 1048576) wout = (const float*)d_in[i];
    }
    float* out = (float*)d_out;

    convert_split<0><<<1024, 256>>>(x,    M_TOT * HID);
    convert_split<1><<<1024, 256>>>(wqkv, 3 * HID * HID);
    convert_split<2><<<1024, 256>>>(wout, HID * HID);

    mma_gemm<0><<<dim3(3 * HID / 128, M_TOT / 128), 256>>>(nullptr);

    prep_attn<<<4096, 256>>>();

    attn_mma<<<dim3(S_ / 64, B_ * HEADS), 128>>>();

    convert_split<3><<<1024, 256>>>(nullptr, M_TOT * HID);
    mma_gemm<1><<<dim3(HID / 128, M_TOT / 128), 256>>>(out);
}

// round 7
// speedup vs baseline: 2.4754x; 1.2401x over previous
#include <cuda_runtime.h>
#include <cuda_bf16.h>
#include <math_constants.h>
#include <cstdint>

// ---------------------------------------------------------------------------
// MHA Round 7: GEMMs get cp.async 2-stage pipeline + 2 CTA/SM occupancy.
// Attention (R6 mma.sync 3-term, proven) unchanged.
// ---------------------------------------------------------------------------

#define B_      2
#define S_      2048
#define HID     1024
#define HEADS   16
#define HD      64
#define M_TOT   (B_ * S_)
#define SCALE   0.125f
#define K3      3072

// fp32 scratch
__device__ float g_Q[B_ * HEADS * S_ * HD];
__device__ float g_K[B_ * HEADS * S_ * HD];
__device__ float g_V[B_ * HEADS * S_ * HD];
__device__ float g_O[M_TOT * HID];

// bf16 extended-K GEMM operands
__device__ __nv_bfloat16 g_Xe[M_TOT * K3];
__device__ __nv_bfloat16 g_We[3 * HID * K3];
__device__ __nv_bfloat16 g_Ue[HID * K3];
__device__ __nv_bfloat16 g_Oe[M_TOT * K3];

// bf16 split attention operands
__device__ __nv_bfloat16 g_Qh[B_ * HEADS * S_ * HD];
__device__ __nv_bfloat16 g_Ql[B_ * HEADS * S_ * HD];
__device__ __nv_bfloat16 g_Kh[B_ * HEADS * S_ * HD];
__device__ __nv_bfloat16 g_Kl[B_ * HEADS * S_ * HD];
__device__ __nv_bfloat16 g_Vth[B_ * HEADS * HD * S_];
__device__ __nv_bfloat16 g_Vtl[B_ * HEADS * HD * S_];

// ---------------------------------------------------------------------------
__device__ __forceinline__ uint32_t smem_u32(const void* p) {
    uint32_t a;
    asm("{ .reg .u64 t; cvta.to.shared.u64 t, %1; cvt.u32.u64 %0, t; }"
        : "=r"(a) : "l"(p));
    return a;
}
__device__ __forceinline__ void ldsm_x4(uint32_t* r, uint32_t addr) {
    asm volatile("ldmatrix.sync.aligned.m8n8.x4.shared.b16 {%0,%1,%2,%3}, [%4];"
        : "=r"(r[0]), "=r"(r[1]), "=r"(r[2]), "=r"(r[3]) : "r"(addr));
}
__device__ __forceinline__ void mma16816(float* d, const uint32_t* a,
                                         uint32_t b0, uint32_t b1) {
    asm volatile(
        "mma.sync.aligned.m16n8k16.row.col.f32.bf16.bf16.f32 "
        "{%0,%1,%2,%3}, {%4,%5,%6,%7}, {%8,%9}, {%0,%1,%2,%3};"
        : "+f"(d[0]), "+f"(d[1]), "+f"(d[2]), "+f"(d[3])
        : "r"(a[0]), "r"(a[1]), "r"(a[2]), "r"(a[3]), "r"(b0), "r"(b1));
}
__device__ __forceinline__ uint32_t sw(uint32_t off) {
    return off ^ ((off >> 3) & 0x70);
}
__device__ __forceinline__ uint32_t pack_bf16(float lo, float hi) {
    __nv_bfloat162 t = __floats2bfloat162_rn(lo, hi);
    return *reinterpret_cast<uint32_t*>(&t);
}
__device__ __forceinline__ void cp16(uint32_t saddr, const void* g) {
    asm volatile("cp.async.cg.shared.global [%0], [%1], 16;"
                 :: "r"(saddr), "l"(g) : "memory");
}
#define CP_COMMIT() asm volatile("cp.async.commit_group;" ::: "memory")
template <int N>
__device__ __forceinline__ void cp_wait() {
    asm volatile("cp.async.wait_group %0;" :: "n"(N) : "memory");
}

// ---------------------------------------------------------------------------
// extended-K converters (R5, proven)
// ---------------------------------------------------------------------------
template <int WHICH>
__global__ void convert_split(const float* __restrict__ src_in, int n)
{
    const float* src;
    __nv_bfloat16* dst;
    if      (WHICH == 0) { src = src_in; dst = g_Xe; }
    else if (WHICH == 1) { src = src_in; dst = g_We; }
    else if (WHICH == 2) { src = src_in; dst = g_Ue; }
    else                 { src = g_O;    dst = g_Oe; }

    for (int i = blockIdx.x * blockDim.x + threadIdx.x; i < n;
         i += gridDim.x * blockDim.x) {
        int m = i >> 10;
        int k = i & 1023;
        float xv = src[i];
        __nv_bfloat16 h = __float2bfloat16(xv);
        __nv_bfloat16 l = __float2bfloat16(xv - __bfloat162float(h));
        size_t base = (size_t)m * K3 + k;
        if (WHICH == 0 || WHICH == 3) {
            dst[base] = h; dst[base + 1024] = h; dst[base + 2048] = l;
        } else {
            dst[base] = h; dst[base + 1024] = l; dst[base + 2048] = h;
        }
    }
}

// ---------------------------------------------------------------------------
// prep: g_Q/g_K/g_V fp32 -> split bf16 attention operands (R6, proven)
// ---------------------------------------------------------------------------
__global__ void prep_attn()
{
    const int n = B_ * HEADS * S_ * HD;
    for (int i = blockIdx.x * blockDim.x + threadIdx.x; i < n;
         i += gridDim.x * blockDim.x) {
        float q = g_Q[i] * SCALE;
        __nv_bfloat16 qh = __float2bfloat16(q);
        g_Qh[i] = qh;
        g_Ql[i] = __float2bfloat16(q - __bfloat162float(qh));

        float k = g_K[i];
        __nv_bfloat16 kh = __float2bfloat16(k);
        g_Kh[i] = kh;
        g_Kl[i] = __float2bfloat16(k - __bfloat162float(kh));

        float v = g_V[i];
        __nv_bfloat16 vh = __float2bfloat16(v);
        int bh = i >> 17;
        int s  = (i >> 6) & 2047;
        int d  = i & 63;
        size_t t = ((size_t)bh * HD + d) * S_ + s;
        g_Vth[t] = vh;
        g_Vtl[t] = __float2bfloat16(v - __bfloat162float(vh));
    }
}

// ---------------------------------------------------------------------------
// Pipelined mma.sync GEMM: C[m,n] = sum_k A'[m,k] * B'[n,k], K'=3072.
// CTA tile 128(M) x 64(N); 8 warps = 2(M, 64 rows) x 4(N, 16 cols);
// warp tile 64x16 -> acc[4][2][4] = 32 regs.
// cp.async 2-stage double buffer, K-chunk 64. Static smem = 48KB exactly.
// MODE 0: A'=g_Xe, B'=g_We (N=3072), scatter epilogue to g_Q/g_K/g_V.
// MODE 1: A'=g_Oe, B'=g_Ue (N=1024), row-major epilogue.
// ---------------------------------------------------------------------------
#define NKT (K3 / 64)    // 48

template <int MODE>
__global__ __launch_bounds__(256, 2) void mma_gemm(float* __restrict__ Cout)
{
    __shared__ __align__(128) __nv_bfloat16 sA[2][128 * 64];  // 2 x 16KB
    __shared__ __align__(128) __nv_bfloat16 sB[2][64 * 64];   // 2 x 8KB

    const int tid = threadIdx.x;
    const int wid = tid >> 5;
    const int lid = tid & 31;
    const int bn = blockIdx.x;
    const int bm = blockIdx.y;
    const int wm = wid & 1;          // M offset wm*64
    const int wn = wid >> 1;         // N offset wn*16

    const __nv_bfloat16* Ag = (MODE == 0) ? g_Xe : g_Oe;
    const __nv_bfloat16* Bg = (MODE == 0) ? g_We : g_Ue;

    const uint32_t aA0 = smem_u32(sA[0]);
    const uint32_t aA1 = smem_u32(sA[1]);
    const uint32_t aB0 = smem_u32(sB[0]);
    const uint32_t aB1 = smem_u32(sB[1]);

    // per-thread load coords
    const int ar = tid >> 1;                 // A row 0..127 (2 chunks/row)
    const int aj = (tid & 1) * 4;            // A 16B-chunk col 0 or 4
    const int br = tid >> 2;                 // B row 0..63 (4 thr/row)... careful
    const int bj = (tid & 3) * 2;            // B 16B-chunk col 0,2,4,6

    // A tile: 128 rows x 8 chunks = 1024 chunks, 256 thr x 4
    // B tile: 64 rows x 8 chunks = 512 chunks, 256 thr x 2
    auto issue_stage = [&](int kt, int buf) {
        const uint32_t dA = buf ? aA1 : aA0;
        const uint32_t dB = buf ? aB1 : aB0;
        const __nv_bfloat16* gA =
            Ag + (size_t)(bm * 128 + ar) * K3 + kt * 64 + aj * 8;
#pragma unroll
        for (int p = 0; p < 4; p++)   // rows ar, cols aj..aj+3? no: 2 chunks x2
            ;
        // A: each thread does 4 chunks: (row ar, col aj + {0,1}) x (row ar+?..)
        // simpler: linear indexing
#pragma unroll
        for (int p = 0; p < 4; p++) {
            int idx = tid + p * 256;          // 0..1023
            int r = idx >> 3, j = idx & 7;
            cp16(dA + sw((uint32_t)(r * 128 + j * 16)),
                 Ag + (size_t)(bm * 128 + r) * K3 + kt * 64 + j * 8);
        }
#pragma unroll
        for (int p = 0; p < 2; p++) {
            int idx = tid + p * 256;          // 0..511
            int r = idx >> 3, j = idx & 7;
            cp16(dB + sw((uint32_t)(r * 128 + j * 16)),
                 Bg + (size_t)(bn * 64 + r) * K3 + kt * 64 + j * 8);
        }
        (void)gA; (void)br; (void)bj;
    };

    float acc[4][2][4];
#pragma unroll
    for (int a = 0; a < 4; a++)
#pragma unroll
        for (int b = 0; b < 2; b++)
#pragma unroll
            for (int c = 0; c < 4; c++) acc[a][b][c] = 0.f;

    const int lrow = lid & 15;
    const int lkb  = lid >> 4;

    // prologue
    issue_stage(0, 0); CP_COMMIT();
    issue_stage(1, 1); CP_COMMIT();

    for (int kt = 0; kt < NKT; kt++) {
        cp_wait<1>();
        __syncthreads();

        const uint32_t cA = (kt & 1) ? aA1 : aA0;
        const uint32_t cB = (kt & 1) ? aB1 : aB0;

#pragma unroll
        for (int ks = 0; ks < 4; ks++) {
            uint32_t afr[4][4], bfr[4];
#pragma unroll
            for (int mi = 0; mi < 4; mi++) {
                uint32_t o = (uint32_t)((wm * 64 + mi * 16 + lrow) * 128 +
                                        ks * 32 + lkb * 16);
                ldsm_x4(afr[mi], cA + sw(o));
            }
            {
                uint32_t o = (uint32_t)((wn * 16 + lrow) * 128 +
                                        ks * 32 + lkb * 16);
                ldsm_x4(bfr, cB + sw(o));
            }
#pragma unroll
            for (int mi = 0; mi < 4; mi++)
#pragma unroll
                for (int ni = 0; ni < 2; ni++)
                    mma16816(acc[mi][ni], afr[mi], bfr[ni], bfr[ni + 2]);
        }

        __syncthreads();
        if (kt + 2 < NKT) issue_stage(kt + 2, kt & 1);
        CP_COMMIT();
    }

    // ---- epilogue ----
    const int tg = lid >> 2;
    const int tc = (lid & 3) * 2;

    if (MODE == 1) {
#pragma unroll
        for (int mi = 0; mi < 4; mi++)
#pragma unroll
            for (int ni = 0; ni < 2; ni++) {
                int m0 = bm * 128 + wm * 64 + mi * 16 + tg;
                int n0 = bn * 64 + wn * 16 + ni * 8 + tc;
                *reinterpret_cast<float2*>(&Cout[(size_t)m0 * HID + n0]) =
                    make_float2(acc[mi][ni][0], acc[mi][ni][1]);
                *reinterpret_cast<float2*>(&Cout[(size_t)(m0 + 8) * HID + n0]) =
                    make_float2(acc[mi][ni][2], acc[mi][ni][3]);
            }
    } else {
#pragma unroll
        for (int mi = 0; mi < 4; mi++)
#pragma unroll
            for (int ni = 0; ni < 2; ni++)
#pragma unroll
                for (int q = 0; q < 4; q++) {
                    int m = bm * 128 + wm * 64 + mi * 16 + tg + (q >> 1) * 8;
                    int e = bn * 64 + wn * 16 + ni * 8 + tc + (q & 1);
                    float val = acc[mi][ni][q];
                    int b = m >> 11, s = m & 2047;
                    int region = e >> 10;
                    int e2 = e & 1023;
                    int h = e2 >> 6, d = e2 & 63;
                    size_t off = ((size_t)(b * HEADS + h) * S_ + s) * HD + d;
                    if      (region == 0) g_Q[off] = val;
                    else if (region == 1) g_K[off] = val;
                    else                  g_V[off] = val;
                }
    }
}

// ---------------------------------------------------------------------------
// Tensor-core flash attention, 3-term hi/lo compensated bf16 (R6, proven).
// ---------------------------------------------------------------------------
__device__ __forceinline__ void load_tile64(__nv_bfloat16* s,
                                            const __nv_bfloat16* g,
                                            int gstride, int tid)
{
#pragma unroll
    for (int p = 0; p < 4; p++) {
        int idx = tid + p * 128;
        int r = idx >> 3, j = idx & 7;
        uint4 v = *reinterpret_cast<const uint4*>(g + (size_t)r * gstride + j * 8);
        *reinterpret_cast<uint4*>(
            reinterpret_cast<char*>(s) + sw((uint32_t)(r * 128 + j * 16))) = v;
    }
}

__global__ __launch_bounds__(128) void attn_mma()
{
    __shared__ __align__(128) __nv_bfloat16 sQh[4096], sQl[4096];
    __shared__ __align__(128) __nv_bfloat16 sKh[4096], sKl[4096];
    __shared__ __align__(128) __nv_bfloat16 sVh[4096], sVl[4096];

    const int tid = threadIdx.x;
    const int wid = tid >> 5;
    const int lid = tid & 31;
    const int qt = blockIdx.x;
    const int bh = blockIdx.y;
    const int b  = bh >> 4;
    const int h  = bh & 15;

    const int lrow = lid & 15;
    const int lkb  = lid >> 4;
    const int tg   = lid >> 2;
    const int tc   = (lid & 3) * 2;

    const size_t qoff = ((size_t)bh * S_ + qt * 64) * HD;
    load_tile64(sQh, g_Qh + qoff, HD, tid);
    load_tile64(sQl, g_Ql + qoff, HD, tid);
    __syncthreads();

    uint32_t qfh[4][4], qfl[4][4];
    const uint32_t aQh = smem_u32(sQh), aQl = smem_u32(sQl);
#pragma unroll
    for (int ks = 0; ks < 4; ks++) {
        uint32_t o = (uint32_t)((wid * 16 + lrow) * 128 + ks * 32 + lkb * 16);
        ldsm_x4(qfh[ks], aQh + sw(o));
        ldsm_x4(qfl[ks], aQl + sw(o));
    }

    float oacc[8][4];
#pragma unroll
    for (int t = 0; t < 8; t++)
#pragma unroll
        for (int c = 0; c < 4; c++) oacc[t][c] = 0.f;
    float m0 = -CUDART_INF_F, m1 = -CUDART_INF_F;
    float l0 = 0.f, l1 = 0.f;

    const uint32_t aKh = smem_u32(sKh), aKl = smem_u32(sKl);
    const uint32_t aVh = smem_u32(sVh), aVl = smem_u32(sVl);

    for (int kt = 0; kt < S_ / 64; kt++) {
        __syncthreads();
        {
            const size_t koff = ((size_t)bh * S_ + kt * 64) * HD;
            load_tile64(sKh, g_Kh + koff, HD, tid);
            load_tile64(sKl, g_Kl + koff, HD, tid);
            const size_t voff = (size_t)bh * HD * S_ + kt * 64;
            load_tile64(sVh, g_Vth + voff, S_, tid);
            load_tile64(sVl, g_Vtl + voff, S_, tid);
        }
        __syncthreads();

        float sacc[8][4];
#pragma unroll
        for (int t = 0; t < 8; t++)
#pragma unroll
            for (int c = 0; c < 4; c++) sacc[t][c] = 0.f;

#pragma unroll
        for (int ks = 0; ks < 4; ks++) {
            uint32_t kbh[4][4], kbl[4][4];
#pragma unroll
            for (int nb = 0; nb < 4; nb++) {
                uint32_t o = (uint32_t)((nb * 16 + lrow) * 128 + ks * 32 + lkb * 16);
                ldsm_x4(kbh[nb], aKh + sw(o));
                ldsm_x4(kbl[nb], aKl + sw(o));
            }
#pragma unroll
            for (int nt = 0; nt < 8; nt++) {
                uint32_t bh0 = kbh[nt >> 1][nt & 1], bh1 = kbh[nt >> 1][(nt & 1) + 2];
                uint32_t bl0 = kbl[nt >> 1][nt & 1], bl1 = kbl[nt >> 1][(nt & 1) + 2];
                mma16816(sacc[nt], qfh[ks], bh0, bh1);
                mma16816(sacc[nt], qfh[ks], bl0, bl1);
                mma16816(sacc[nt], qfl[ks], bh0, bh1);
            }
        }

        float rm0 = -CUDART_INF_F, rm1 = -CUDART_INF_F;
#pragma unroll
        for (int t = 0; t < 8; t++) {
            rm0 = fmaxf(rm0, fmaxf(sacc[t][0], sacc[t][1]));
            rm1 = fmaxf(rm1, fmaxf(sacc[t][2], sacc[t][3]));
        }
        rm0 = fmaxf(rm0, __shfl_xor_sync(0xffffffffu, rm0, 1));
        rm0 = fmaxf(rm0, __shfl_xor_sync(0xffffffffu, rm0, 2));
        rm1 = fmaxf(rm1, __shfl_xor_sync(0xffffffffu, rm1, 1));
        rm1 = fmaxf(rm1, __shfl_xor_sync(0xffffffffu, rm1, 2));

        float mn0 = fmaxf(m0, rm0), mn1 = fmaxf(m1, rm1);
        float cr0 = __expf(m0 - mn0), cr1 = __expf(m1 - mn1);
        m0 = mn0; m1 = mn1;

        float rs0 = 0.f, rs1 = 0.f;
#pragma unroll
        for (int t = 0; t < 8; t++) {
            sacc[t][0] = __expf(sacc[t][0] - mn0);
            sacc[t][1] = __expf(sacc[t][1] - mn0);
            sacc[t][2] = __expf(sacc[t][2] - mn1);
            sacc[t][3] = __expf(sacc[t][3] - mn1);
            rs0 += sacc[t][0] + sacc[t][1];
            rs1 += sacc[t][2] + sacc[t][3];
        }
        rs0 += __shfl_xor_sync(0xffffffffu, rs0, 1);
        rs0 += __shfl_xor_sync(0xffffffffu, rs0, 2);
        rs1 += __shfl_xor_sync(0xffffffffu, rs1, 1);
        rs1 += __shfl_xor_sync(0xffffffffu, rs1, 2);
        l0 = l0 * cr0 + rs0;
        l1 = l1 * cr1 + rs1;

#pragma unroll
        for (int t = 0; t < 8; t++) {
            oacc[t][0] *= cr0; oacc[t][1] *= cr0;
            oacc[t][2] *= cr1; oacc[t][3] *= cr1;
        }

        uint32_t pah[4][4], pal[4][4];
#pragma unroll
        for (int ks = 0; ks < 4; ks++) {
            const int t0 = 2 * ks, t1 = 2 * ks + 1;
            float ph[8], pl[8];
            const float pv[8] = {sacc[t0][0], sacc[t0][1], sacc[t0][2], sacc[t0][3],
                                 sacc[t1][0], sacc[t1][1], sacc[t1][2], sacc[t1][3]};
#pragma unroll
            for (int e = 0; e < 8; e++) {
                __nv_bfloat16 hb = __float2bfloat16(pv[e]);
                ph[e] = __bfloat162float(hb);
                pl[e] = pv[e] - ph[e];
            }
            pah[ks][0] = pack_bf16(ph[0], ph[1]);
            pah[ks][1] = pack_bf16(ph[2], ph[3]);
            pah[ks][2] = pack_bf16(ph[4], ph[5]);
            pah[ks][3] = pack_bf16(ph[6], ph[7]);
            pal[ks][0] = pack_bf16(pl[0], pl[1]);
            pal[ks][1] = pack_bf16(pl[2], pl[3]);
            pal[ks][2] = pack_bf16(pl[4], pl[5]);
            pal[ks][3] = pack_bf16(pl[6], pl[7]);
        }

#pragma unroll
        for (int ks = 0; ks < 4; ks++) {
            uint32_t vbh[4][4], vbl[4][4];
#pragma unroll
            for (int nb = 0; nb < 4; nb++) {
                uint32_t o = (uint32_t)((nb * 16 + lrow) * 128 + ks * 32 + lkb * 16);
                ldsm_x4(vbh[nb], aVh + sw(o));
                ldsm_x4(vbl[nb], aVl + sw(o));
            }
#pragma unroll
            for (int nt = 0; nt < 8; nt++) {
                uint32_t bh0 = vbh[nt >> 1][nt & 1], bh1 = vbh[nt >> 1][(nt & 1) + 2];
                uint32_t bl0 = vbl[nt >> 1][nt & 1], bl1 = vbl[nt >> 1][(nt & 1) + 2];
                mma16816(oacc[nt], pah[ks], bh0, bh1);
                mma16816(oacc[nt], pah[ks], bl0, bl1);
                mma16816(oacc[nt], pal[ks], bh0, bh1);
            }
        }
    }

    const float inv0 = 1.f / l0, inv1 = 1.f / l1;
    const int r0 = qt * 64 + wid * 16 + tg;
#pragma unroll
    for (int nt = 0; nt < 8; nt++) {
        int col = h * 64 + nt * 8 + tc;
        *reinterpret_cast<float2*>(&g_O[(size_t)(b * S_ + r0) * HID + col]) =
            make_float2(oacc[nt][0] * inv0, oacc[nt][1] * inv0);
        *reinterpret_cast<float2*>(&g_O[(size_t)(b * S_ + r0 + 8) * HID + col]) =
            make_float2(oacc[nt][2] * inv1, oacc[nt][3] * inv1);
    }
}

// ---------------------------------------------------------------------------
extern "C" void kernel_launch(void* const* d_in, const int* in_sizes, int n_in,
                              void* d_out, int out_size)
{
    const float* x    = (const float*)d_in[0];
    const float* wqkv = (const float*)d_in[1];
    const float* wout = (const float*)d_in[2];
    for (int i = 0; i < n_in; i++) {
        if      (in_sizes[i] == 4194304) x    = (const float*)d_in[i];
        else if (in_sizes[i] == 3145728) wqkv = (const float*)d_in[i];
        else if (in_sizes[i] == 1048576) wout = (const float*)d_in[i];
    }
    float* out = (float*)d_out;

    convert_split<0><<<1024, 256>>>(x,    M_TOT * HID);
    convert_split<1><<<1024, 256>>>(wqkv, 3 * HID * HID);
    convert_split<2><<<1024, 256>>>(wout, HID * HID);

    mma_gemm<0><<<dim3(3 * HID / 64, M_TOT / 128), 256>>>(nullptr);

    prep_attn<<<4096, 256>>>();

    attn_mma<<<dim3(S_ / 64, B_ * HEADS), 128>>>();

    convert_split<3><<<1024, 256>>>(nullptr, M_TOT * HID);
    mma_gemm<1><<<dim3(HID / 64, M_TOT / 128), 256>>>(out);
}

// round 8
// speedup vs baseline: 2.8740x; 1.1610x over previous
#include <cuda_runtime.h>
#include <cuda_bf16.h>
#include <math_constants.h>
#include <cstdint>

// ---------------------------------------------------------------------------
// MHA Round 8: attention gets zero-extra-smem cp.async software pipeline;
// prep/convert kernels fused into GEMM & attention epilogues.
// ---------------------------------------------------------------------------

#define B_      2
#define S_      2048
#define HID     1024
#define HEADS   16
#define HD      64
#define M_TOT   (B_ * S_)
#define SCALE   0.125f
#define K3      3072

// bf16 extended-K GEMM operands
__device__ __nv_bfloat16 g_Xe[M_TOT * K3];
__device__ __nv_bfloat16 g_We[3 * HID * K3];
__device__ __nv_bfloat16 g_Ue[HID * K3];
__device__ __nv_bfloat16 g_Oe[M_TOT * K3];

// bf16 split attention operands (written by gemm<0> epilogue)
__device__ __nv_bfloat16 g_Qh[B_ * HEADS * S_ * HD];   // [bh][s][d], scale folded
__device__ __nv_bfloat16 g_Ql[B_ * HEADS * S_ * HD];
__device__ __nv_bfloat16 g_Kh[B_ * HEADS * S_ * HD];
__device__ __nv_bfloat16 g_Kl[B_ * HEADS * S_ * HD];
__device__ __nv_bfloat16 g_Vth[B_ * HEADS * HD * S_];  // [bh][d][s]
__device__ __nv_bfloat16 g_Vtl[B_ * HEADS * HD * S_];

// ---------------------------------------------------------------------------
__device__ __forceinline__ uint32_t smem_u32(const void* p) {
    uint32_t a;
    asm("{ .reg .u64 t; cvta.to.shared.u64 t, %1; cvt.u32.u64 %0, t; }"
        : "=r"(a) : "l"(p));
    return a;
}
__device__ __forceinline__ void ldsm_x4(uint32_t* r, uint32_t addr) {
    asm volatile("ldmatrix.sync.aligned.m8n8.x4.shared.b16 {%0,%1,%2,%3}, [%4];"
        : "=r"(r[0]), "=r"(r[1]), "=r"(r[2]), "=r"(r[3]) : "r"(addr));
}
__device__ __forceinline__ void mma16816(float* d, const uint32_t* a,
                                         uint32_t b0, uint32_t b1) {
    asm volatile(
        "mma.sync.aligned.m16n8k16.row.col.f32.bf16.bf16.f32 "
        "{%0,%1,%2,%3}, {%4,%5,%6,%7}, {%8,%9}, {%0,%1,%2,%3};"
        : "+f"(d[0]), "+f"(d[1]), "+f"(d[2]), "+f"(d[3])
        : "r"(a[0]), "r"(a[1]), "r"(a[2]), "r"(a[3]), "r"(b0), "r"(b1));
}
__device__ __forceinline__ uint32_t sw(uint32_t off) {
    return off ^ ((off >> 3) & 0x70);
}
__device__ __forceinline__ uint32_t pack_bf16(float lo, float hi) {
    __nv_bfloat162 t = __floats2bfloat162_rn(lo, hi);
    return *reinterpret_cast<uint32_t*>(&t);
}
__device__ __forceinline__ void cp16(uint32_t saddr, const void* g) {
    asm volatile("cp.async.cg.shared.global [%0], [%1], 16;"
                 :: "r"(saddr), "l"(g) : "memory");
}
#define CP_COMMIT() asm volatile("cp.async.commit_group;" ::: "memory")
template <int N>
__device__ __forceinline__ void cp_wait() {
    asm volatile("cp.async.wait_group %0;" :: "n"(N) : "memory");
}

// ---------------------------------------------------------------------------
// extended-K converters (inputs only)
// ---------------------------------------------------------------------------
template <int WHICH>
__global__ void convert_split(const float* __restrict__ src, int n)
{
    __nv_bfloat16* dst;
    if      (WHICH == 0) dst = g_Xe;
    else if (WHICH == 1) dst = g_We;
    else                 dst = g_Ue;

    for (int i = blockIdx.x * blockDim.x + threadIdx.x; i < n;
         i += gridDim.x * blockDim.x) {
        int m = i >> 10;
        int k = i & 1023;
        float xv = src[i];
        __nv_bfloat16 h = __float2bfloat16(xv);
        __nv_bfloat16 l = __float2bfloat16(xv - __bfloat162float(h));
        size_t base = (size_t)m * K3 + k;
        if (WHICH == 0) {   // A-pattern
            dst[base] = h; dst[base + 1024] = h; dst[base + 2048] = l;
        } else {            // B-pattern
            dst[base] = h; dst[base + 1024] = l; dst[base + 2048] = h;
        }
    }
}

// ---------------------------------------------------------------------------
// Pipelined mma.sync GEMM (R7, proven). CTA 128x64, 8 warps, cp.async 2-stage.
// MODE 0: A'=g_Xe, B'=g_We (N=3072); epilogue writes split-bf16 Q/K/V direct.
// MODE 1: A'=g_Oe, B'=g_Ue (N=1024); row-major fp32 epilogue -> d_out.
// ---------------------------------------------------------------------------
#define NKT (K3 / 64)    // 48

template <int MODE>
__global__ __launch_bounds__(256, 2) void mma_gemm(float* __restrict__ Cout)
{
    __shared__ __align__(128) __nv_bfloat16 sA[2][128 * 64];
    __shared__ __align__(128) __nv_bfloat16 sB[2][64 * 64];

    const int tid = threadIdx.x;
    const int wid = tid >> 5;
    const int lid = tid & 31;
    const int bn = blockIdx.x;
    const int bm = blockIdx.y;
    const int wm = wid & 1;
    const int wn = wid >> 1;

    const __nv_bfloat16* Ag = (MODE == 0) ? g_Xe : g_Oe;
    const __nv_bfloat16* Bg = (MODE == 0) ? g_We : g_Ue;

    const uint32_t aA0 = smem_u32(sA[0]);
    const uint32_t aA1 = smem_u32(sA[1]);
    const uint32_t aB0 = smem_u32(sB[0]);
    const uint32_t aB1 = smem_u32(sB[1]);

    auto issue_stage = [&](int kt, int buf) {
        const uint32_t dA = buf ? aA1 : aA0;
        const uint32_t dB = buf ? aB1 : aB0;
#pragma unroll
        for (int p = 0; p < 4; p++) {
            int idx = tid + p * 256;
            int r = idx >> 3, j = idx & 7;
            cp16(dA + sw((uint32_t)(r * 128 + j * 16)),
                 Ag + (size_t)(bm * 128 + r) * K3 + kt * 64 + j * 8);
        }
#pragma unroll
        for (int p = 0; p < 2; p++) {
            int idx = tid + p * 256;
            int r = idx >> 3, j = idx & 7;
            cp16(dB + sw((uint32_t)(r * 128 + j * 16)),
                 Bg + (size_t)(bn * 64 + r) * K3 + kt * 64 + j * 8);
        }
    };

    float acc[4][2][4];
#pragma unroll
    for (int a = 0; a < 4; a++)
#pragma unroll
        for (int b = 0; b < 2; b++)
#pragma unroll
            for (int c = 0; c < 4; c++) acc[a][b][c] = 0.f;

    const int lrow = lid & 15;
    const int lkb  = lid >> 4;

    issue_stage(0, 0); CP_COMMIT();
    issue_stage(1, 1); CP_COMMIT();

    for (int kt = 0; kt < NKT; kt++) {
        cp_wait<1>();
        __syncthreads();

        const uint32_t cA = (kt & 1) ? aA1 : aA0;
        const uint32_t cB = (kt & 1) ? aB1 : aB0;

#pragma unroll
        for (int ks = 0; ks < 4; ks++) {
            uint32_t afr[4][4], bfr[4];
#pragma unroll
            for (int mi = 0; mi < 4; mi++) {
                uint32_t o = (uint32_t)((wm * 64 + mi * 16 + lrow) * 128 +
                                        ks * 32 + lkb * 16);
                ldsm_x4(afr[mi], cA + sw(o));
            }
            {
                uint32_t o = (uint32_t)((wn * 16 + lrow) * 128 +
                                        ks * 32 + lkb * 16);
                ldsm_x4(bfr, cB + sw(o));
            }
#pragma unroll
            for (int mi = 0; mi < 4; mi++)
#pragma unroll
                for (int ni = 0; ni < 2; ni++)
                    mma16816(acc[mi][ni], afr[mi], bfr[ni], bfr[ni + 2]);
        }

        __syncthreads();
        if (kt + 2 < NKT) issue_stage(kt + 2, kt & 1);
        CP_COMMIT();
    }

    const int tg = lid >> 2;
    const int tc = (lid & 3) * 2;

    if (MODE == 1) {
#pragma unroll
        for (int mi = 0; mi < 4; mi++)
#pragma unroll
            for (int ni = 0; ni < 2; ni++) {
                int m0 = bm * 128 + wm * 64 + mi * 16 + tg;
                int n0 = bn * 64 + wn * 16 + ni * 8 + tc;
                *reinterpret_cast<float2*>(&Cout[(size_t)m0 * HID + n0]) =
                    make_float2(acc[mi][ni][0], acc[mi][ni][1]);
                *reinterpret_cast<float2*>(&Cout[(size_t)(m0 + 8) * HID + n0]) =
                    make_float2(acc[mi][ni][2], acc[mi][ni][3]);
            }
    } else {
        // fused split-bf16 epilogue: Q (scaled) / K / V(transposed)
#pragma unroll
        for (int mi = 0; mi < 4; mi++)
#pragma unroll
            for (int ni = 0; ni < 2; ni++)
#pragma unroll
                for (int q = 0; q < 4; q++) {
                    int m = bm * 128 + wm * 64 + mi * 16 + tg + (q >> 1) * 8;
                    int e = bn * 64 + wn * 16 + ni * 8 + tc + (q & 1);
                    float val = acc[mi][ni][q];
                    int b = m >> 11, s = m & 2047;
                    int region = e >> 10;
                    int e2 = e & 1023;
                    int h = e2 >> 6, d = e2 & 63;
                    int bh = b * HEADS + h;
                    if (region == 0) {
                        float qv = val * SCALE;
                        __nv_bfloat16 hv = __float2bfloat16(qv);
                        size_t off = ((size_t)bh * S_ + s) * HD + d;
                        g_Qh[off] = hv;
                        g_Ql[off] = __float2bfloat16(qv - __bfloat162float(hv));
                    } else if (region == 1) {
                        __nv_bfloat16 hv = __float2bfloat16(val);
                        size_t off = ((size_t)bh * S_ + s) * HD + d;
                        g_Kh[off] = hv;
                        g_Kl[off] = __float2bfloat16(val - __bfloat162float(hv));
                    } else {
                        __nv_bfloat16 hv = __float2bfloat16(val);
                        size_t off = ((size_t)bh * HD + d) * S_ + s;
                        g_Vth[off] = hv;
                        g_Vtl[off] = __float2bfloat16(val - __bfloat162float(hv));
                    }
                }
    }
}

// ---------------------------------------------------------------------------
// Tensor-core flash attention, 3-term hi/lo bf16, cp.async software pipeline.
// 128 threads, 48KB static smem (Qh,Ql,Kh,Kl,Vh,Vl @ 8KB each).
// K(kt+1) issued after S-compute (overlaps softmax+PV);
// V(kt+1) issued after PV (overlaps next S-compute).
// Epilogue writes g_Oe directly in extended-K [hi|hi|lo] layout.
// ---------------------------------------------------------------------------
__device__ __forceinline__ void cp_tile64(uint32_t sdst,
                                          const __nv_bfloat16* g,
                                          int gstride, int tid)
{
#pragma unroll
    for (int p = 0; p < 4; p++) {
        int idx = tid + p * 128;          // 0..511
        int r = idx >> 3, j = idx & 7;
        cp16(sdst + sw((uint32_t)(r * 128 + j * 16)),
             g + (size_t)r * gstride + j * 8);
    }
}

__global__ __launch_bounds__(128) void attn_mma()
{
    __shared__ __align__(128) __nv_bfloat16 sQh[4096], sQl[4096];
    __shared__ __align__(128) __nv_bfloat16 sKh[4096], sKl[4096];
    __shared__ __align__(128) __nv_bfloat16 sVh[4096], sVl[4096];

    const int tid = threadIdx.x;
    const int wid = tid >> 5;
    const int lid = tid & 31;
    const int qt = blockIdx.x;
    const int bh = blockIdx.y;
    const int b  = bh >> 4;
    const int h  = bh & 15;

    const int lrow = lid & 15;
    const int lkb  = lid >> 4;
    const int tg   = lid >> 2;
    const int tc   = (lid & 3) * 2;

    const uint32_t aQh = smem_u32(sQh), aQl = smem_u32(sQl);
    const uint32_t aKh = smem_u32(sKh), aKl = smem_u32(sKl);
    const uint32_t aVh = smem_u32(sVh), aVl = smem_u32(sVl);

    const __nv_bfloat16* Kh = g_Kh + (size_t)bh * S_ * HD;
    const __nv_bfloat16* Kl = g_Kl + (size_t)bh * S_ * HD;
    const __nv_bfloat16* Vh = g_Vth + (size_t)bh * HD * S_;
    const __nv_bfloat16* Vl = g_Vtl + (size_t)bh * HD * S_;

    // Q load (cp.async) + prologue K(0), V(0)
    const size_t qoff = ((size_t)bh * S_ + qt * 64) * HD;
    cp_tile64(aQh, g_Qh + qoff, HD, tid);
    cp_tile64(aQl, g_Ql + qoff, HD, tid);
    cp_tile64(aKh, Kh, HD, tid);
    cp_tile64(aKl, Kl, HD, tid);
    CP_COMMIT();                                   // group: [Q,K0]
    cp_tile64(aVh, Vh, S_, tid);
    cp_tile64(aVl, Vl, S_, tid);
    CP_COMMIT();                                   // group: [V0]

    cp_wait<1>();                                  // Q,K0 done
    __syncthreads();

    uint32_t qfh[4][4], qfl[4][4];
#pragma unroll
    for (int ks = 0; ks < 4; ks++) {
        uint32_t o = (uint32_t)((wid * 16 + lrow) * 128 + ks * 32 + lkb * 16);
        ldsm_x4(qfh[ks], aQh + sw(o));
        ldsm_x4(qfl[ks], aQl + sw(o));
    }

    float oacc[8][4];
#pragma unroll
    for (int t = 0; t < 8; t++)
#pragma unroll
        for (int c = 0; c < 4; c++) oacc[t][c] = 0.f;
    float m0 = -CUDART_INF_F, m1 = -CUDART_INF_F;
    float l0 = 0.f, l1 = 0.f;

    const int NT = S_ / 64;
    for (int kt = 0; kt < NT; kt++) {
        // K(kt) is ready (prologue or previous commit); V(kt) may be in flight.
        // ---- S = Q K^T, 3-term ----
        float sacc[8][4];
#pragma unroll
        for (int t = 0; t < 8; t++)
#pragma unroll
            for (int c = 0; c < 4; c++) sacc[t][c] = 0.f;

#pragma unroll
        for (int ks = 0; ks < 4; ks++) {
            uint32_t kbh[4][4], kbl[4][4];
#pragma unroll
            for (int nb = 0; nb < 4; nb++) {
                uint32_t o = (uint32_t)((nb * 16 + lrow) * 128 + ks * 32 + lkb * 16);
                ldsm_x4(kbh[nb], aKh + sw(o));
                ldsm_x4(kbl[nb], aKl + sw(o));
            }
#pragma unroll
            for (int nt = 0; nt < 8; nt++) {
                uint32_t bh0 = kbh[nt >> 1][nt & 1], bh1 = kbh[nt >> 1][(nt & 1) + 2];
                uint32_t bl0 = kbl[nt >> 1][nt & 1], bl1 = kbl[nt >> 1][(nt & 1) + 2];
                mma16816(sacc[nt], qfh[ks], bh0, bh1);
                mma16816(sacc[nt], qfh[ks], bl0, bl1);
                mma16816(sacc[nt], qfl[ks], bh0, bh1);
            }
        }

        __syncthreads();              // all warps done reading K tile
        if (kt + 1 < NT)
        {
            cp_tile64(aKh, Kh + (size_t)(kt + 1) * 64 * HD, HD, tid);
            cp_tile64(aKl, Kl + (size_t)(kt + 1) * 64 * HD, HD, tid);
        }
        CP_COMMIT();                  // pending: [V(kt), K(kt+1)]

        // ---- online softmax ----
        float rm0 = -CUDART_INF_F, rm1 = -CUDART_INF_F;
#pragma unroll
        for (int t = 0; t < 8; t++) {
            rm0 = fmaxf(rm0, fmaxf(sacc[t][0], sacc[t][1]));
            rm1 = fmaxf(rm1, fmaxf(sacc[t][2], sacc[t][3]));
        }
        rm0 = fmaxf(rm0, __shfl_xor_sync(0xffffffffu, rm0, 1));
        rm0 = fmaxf(rm0, __shfl_xor_sync(0xffffffffu, rm0, 2));
        rm1 = fmaxf(rm1, __shfl_xor_sync(0xffffffffu, rm1, 1));
        rm1 = fmaxf(rm1, __shfl_xor_sync(0xffffffffu, rm1, 2));

        float mn0 = fmaxf(m0, rm0), mn1 = fmaxf(m1, rm1);
        float cr0 = __expf(m0 - mn0), cr1 = __expf(m1 - mn1);
        m0 = mn0; m1 = mn1;

        float rs0 = 0.f, rs1 = 0.f;
#pragma unroll
        for (int t = 0; t < 8; t++) {
            sacc[t][0] = __expf(sacc[t][0] - mn0);
            sacc[t][1] = __expf(sacc[t][1] - mn0);
            sacc[t][2] = __expf(sacc[t][2] - mn1);
            sacc[t][3] = __expf(sacc[t][3] - mn1);
            rs0 += sacc[t][0] + sacc[t][1];
            rs1 += sacc[t][2] + sacc[t][3];
        }
        rs0 += __shfl_xor_sync(0xffffffffu, rs0, 1);
        rs0 += __shfl_xor_sync(0xffffffffu, rs0, 2);
        rs1 += __shfl_xor_sync(0xffffffffu, rs1, 1);
        rs1 += __shfl_xor_sync(0xffffffffu, rs1, 2);
        l0 = l0 * cr0 + rs0;
        l1 = l1 * cr1 + rs1;

#pragma unroll
        for (int t = 0; t < 8; t++) {
            oacc[t][0] *= cr0; oacc[t][1] *= cr0;
            oacc[t][2] *= cr1; oacc[t][3] *= cr1;
        }

        // ---- pack P (hi/lo) ----
        uint32_t pah[4][4], pal[4][4];
#pragma unroll
        for (int ks = 0; ks < 4; ks++) {
            const int t0 = 2 * ks, t1 = 2 * ks + 1;
            float ph[8], pl[8];
            const float pv[8] = {sacc[t0][0], sacc[t0][1], sacc[t0][2], sacc[t0][3],
                                 sacc[t1][0], sacc[t1][1], sacc[t1][2], sacc[t1][3]};
#pragma unroll
            for (int e = 0; e < 8; e++) {
                __nv_bfloat16 hb = __float2bfloat16(pv[e]);
                ph[e] = __bfloat162float(hb);
                pl[e] = pv[e] - ph[e];
            }
            pah[ks][0] = pack_bf16(ph[0], ph[1]);
            pah[ks][1] = pack_bf16(ph[2], ph[3]);
            pah[ks][2] = pack_bf16(ph[4], ph[5]);
            pah[ks][3] = pack_bf16(ph[6], ph[7]);
            pal[ks][0] = pack_bf16(pl[0], pl[1]);
            pal[ks][1] = pack_bf16(pl[2], pl[3]);
            pal[ks][2] = pack_bf16(pl[4], pl[5]);
            pal[ks][3] = pack_bf16(pl[6], pl[7]);
        }

        cp_wait<1>();                 // V(kt) done; K(kt+1) may be in flight
        __syncthreads();

        // ---- O += P V, 3-term ----
#pragma unroll
        for (int ks = 0; ks < 4; ks++) {
            uint32_t vbh[4][4], vbl[4][4];
#pragma unroll
            for (int nb = 0; nb < 4; nb++) {
                uint32_t o = (uint32_t)((nb * 16 + lrow) * 128 + ks * 32 + lkb * 16);
                ldsm_x4(vbh[nb], aVh + sw(o));
                ldsm_x4(vbl[nb], aVl + sw(o));
            }
#pragma unroll
            for (int nt = 0; nt < 8; nt++) {
                uint32_t bh0 = vbh[nt >> 1][nt & 1], bh1 = vbh[nt >> 1][(nt & 1) + 2];
                uint32_t bl0 = vbl[nt >> 1][nt & 1], bl1 = vbl[nt >> 1][(nt & 1) + 2];
                mma16816(oacc[nt], pah[ks], bh0, bh1);
                mma16816(oacc[nt], pah[ks], bl0, bl1);
                mma16816(oacc[nt], pal[ks], bh0, bh1);
            }
        }

        __syncthreads();              // all warps done reading V tile
        if (kt + 1 < NT)
        {
            cp_tile64(aVh, Vh + (size_t)(kt + 1) * 64, S_, tid);
            cp_tile64(aVl, Vl + (size_t)(kt + 1) * 64, S_, tid);
        }
        CP_COMMIT();                  // pending: [K(kt+1), V(kt+1)]
        cp_wait<1>();                 // K(kt+1) ready for next S
        __syncthreads();
    }

    // ---- epilogue: write g_Oe directly (extended-K A-pattern [hi|hi|lo]) ----
    const float inv0 = 1.f / l0, inv1 = 1.f / l1;
    const int r0 = qt * 64 + wid * 16 + tg;
    const int m0row = b * S_ + r0;
#pragma unroll
    for (int nt = 0; nt < 8; nt++) {
        int col = h * 64 + nt * 8 + tc;
#pragma unroll
        for (int q = 0; q < 4; q++) {
            int m = m0row + (q >> 1) * 8;
            int k = col + (q & 1);
            float val = oacc[nt][q] * ((q < 2) ? inv0 : inv1);
            __nv_bfloat16 hv = __float2bfloat16(val);
            size_t base = (size_t)m * K3 + k;
            g_Oe[base]        = hv;
            g_Oe[base + 1024] = hv;
            g_Oe[base + 2048] = __float2bfloat16(val - __bfloat162float(hv));
        }
    }
}

// ---------------------------------------------------------------------------
extern "C" void kernel_launch(void* const* d_in, const int* in_sizes, int n_in,
                              void* d_out, int out_size)
{
    const float* x    = (const float*)d_in[0];
    const float* wqkv = (const float*)d_in[1];
    const float* wout = (const float*)d_in[2];
    for (int i = 0; i < n_in; i++) {
        if      (in_sizes[i] == 4194304) x    = (const float*)d_in[i];
        else if (in_sizes[i] == 3145728) wqkv = (const float*)d_in[i];
        else if (in_sizes[i] == 1048576) wout = (const float*)d_in[i];
    }
    float* out = (float*)d_out;

    convert_split<0><<<1024, 256>>>(x,    M_TOT * HID);
    convert_split<1><<<1024, 256>>>(wqkv, 3 * HID * HID);
    convert_split<2><<<1024, 256>>>(wout, HID * HID);

    mma_gemm<0><<<dim3(3 * HID / 64, M_TOT / 128), 256>>>(nullptr);

    attn_mma<<<dim3(S_ / 64, B_ * HEADS), 128>>>();

    mma_gemm<1><<<dim3(HID / 64, M_TOT / 128), 256>>>(out);
}

// round 9
// speedup vs baseline: 3.0475x; 1.0604x over previous
#include <cuda_runtime.h>
#include <cuda_bf16.h>
#include <math_constants.h>
#include <cstdint>

// ---------------------------------------------------------------------------
// MHA Round 9: GEMM warp layout 4Mx2N (fewer ldsm per mma), attention
// occupancy 3 CTAs/SM, converters merged into one launch.
// ---------------------------------------------------------------------------

#define B_      2
#define S_      2048
#define HID     1024
#define HEADS   16
#define HD      64
#define M_TOT   (B_ * S_)
#define SCALE   0.125f
#define K3      3072

// bf16 extended-K GEMM operands
__device__ __nv_bfloat16 g_Xe[M_TOT * K3];
__device__ __nv_bfloat16 g_We[3 * HID * K3];
__device__ __nv_bfloat16 g_Ue[HID * K3];
__device__ __nv_bfloat16 g_Oe[M_TOT * K3];

// bf16 split attention operands (written by gemm<0> epilogue)
__device__ __nv_bfloat16 g_Qh[B_ * HEADS * S_ * HD];
__device__ __nv_bfloat16 g_Ql[B_ * HEADS * S_ * HD];
__device__ __nv_bfloat16 g_Kh[B_ * HEADS * S_ * HD];
__device__ __nv_bfloat16 g_Kl[B_ * HEADS * S_ * HD];
__device__ __nv_bfloat16 g_Vth[B_ * HEADS * HD * S_];
__device__ __nv_bfloat16 g_Vtl[B_ * HEADS * HD * S_];

// ---------------------------------------------------------------------------
__device__ __forceinline__ uint32_t smem_u32(const void* p) {
    uint32_t a;
    asm("{ .reg .u64 t; cvta.to.shared.u64 t, %1; cvt.u32.u64 %0, t; }"
        : "=r"(a) : "l"(p));
    return a;
}
__device__ __forceinline__ void ldsm_x4(uint32_t* r, uint32_t addr) {
    asm volatile("ldmatrix.sync.aligned.m8n8.x4.shared.b16 {%0,%1,%2,%3}, [%4];"
        : "=r"(r[0]), "=r"(r[1]), "=r"(r[2]), "=r"(r[3]) : "r"(addr));
}
__device__ __forceinline__ void mma16816(float* d, const uint32_t* a,
                                         uint32_t b0, uint32_t b1) {
    asm volatile(
        "mma.sync.aligned.m16n8k16.row.col.f32.bf16.bf16.f32 "
        "{%0,%1,%2,%3}, {%4,%5,%6,%7}, {%8,%9}, {%0,%1,%2,%3};"
        : "+f"(d[0]), "+f"(d[1]), "+f"(d[2]), "+f"(d[3])
        : "r"(a[0]), "r"(a[1]), "r"(a[2]), "r"(a[3]), "r"(b0), "r"(b1));
}
__device__ __forceinline__ uint32_t sw(uint32_t off) {
    return off ^ ((off >> 3) & 0x70);
}
__device__ __forceinline__ uint32_t pack_bf16(float lo, float hi) {
    __nv_bfloat162 t = __floats2bfloat162_rn(lo, hi);
    return *reinterpret_cast<uint32_t*>(&t);
}
__device__ __forceinline__ void cp16(uint32_t saddr, const void* g) {
    asm volatile("cp.async.cg.shared.global [%0], [%1], 16;"
                 :: "r"(saddr), "l"(g) : "memory");
}
#define CP_COMMIT() asm volatile("cp.async.commit_group;" ::: "memory")
template <int N>
__device__ __forceinline__ void cp_wait() {
    asm volatile("cp.async.wait_group %0;" :: "n"(N) : "memory");
}

// ---------------------------------------------------------------------------
// merged extended-K converter: x -> g_Xe (A-pat), wqkv -> g_We, wout -> g_Ue
// ---------------------------------------------------------------------------
#define NX (M_TOT * HID)          // 4194304
#define NW (3 * HID * HID)        // 3145728
#define NU (HID * HID)            // 1048576

__global__ void convert_all(const float* __restrict__ x,
                            const float* __restrict__ wqkv,
                            const float* __restrict__ wout)
{
    const int ntot = NX + NW + NU;
    for (int i = blockIdx.x * blockDim.x + threadIdx.x; i < ntot;
         i += gridDim.x * blockDim.x) {
        const float* src;
        __nv_bfloat16* dst;
        int j, apat;
        if (i < NX)           { src = x;    dst = g_Xe; j = i;            apat = 1; }
        else if (i < NX + NW) { src = wqkv; dst = g_We; j = i - NX;       apat = 0; }
        else                  { src = wout; dst = g_Ue; j = i - NX - NW;  apat = 0; }
        int m = j >> 10;
        int k = j & 1023;
        float xv = src[j];
        __nv_bfloat16 h = __float2bfloat16(xv);
        __nv_bfloat16 l = __float2bfloat16(xv - __bfloat162float(h));
        size_t base = (size_t)m * K3 + k;
        dst[base] = h;
        if (apat) { dst[base + 1024] = h; dst[base + 2048] = l; }
        else      { dst[base + 1024] = l; dst[base + 2048] = h; }
    }
}

// ---------------------------------------------------------------------------
// Pipelined mma.sync GEMM. CTA 128x64, 8 warps = 4(M)x2(N), warp tile 32x32.
// cp.async 2-stage, K-chunk 64. Per k16-step: 2 A-ldsm + 2 B-ldsm, 8 mma.
// MODE 0: epilogue writes split-bf16 Q/K/V. MODE 1: fp32 row-major -> out.
// ---------------------------------------------------------------------------
#define NKT (K3 / 64)    // 48

template <int MODE>
__global__ __launch_bounds__(256, 2) void mma_gemm(float* __restrict__ Cout)
{
    __shared__ __align__(128) __nv_bfloat16 sA[2][128 * 64];
    __shared__ __align__(128) __nv_bfloat16 sB[2][64 * 64];

    const int tid = threadIdx.x;
    const int wid = tid >> 5;
    const int lid = tid & 31;
    const int bn = blockIdx.x;
    const int bm = blockIdx.y;
    const int wm = wid & 3;          // M offset wm*32
    const int wn = wid >> 2;         // N offset wn*32

    const __nv_bfloat16* Ag = (MODE == 0) ? g_Xe : g_Oe;
    const __nv_bfloat16* Bg = (MODE == 0) ? g_We : g_Ue;

    const uint32_t aA0 = smem_u32(sA[0]);
    const uint32_t aA1 = smem_u32(sA[1]);
    const uint32_t aB0 = smem_u32(sB[0]);
    const uint32_t aB1 = smem_u32(sB[1]);

    auto issue_stage = [&](int kt, int buf) {
        const uint32_t dA = buf ? aA1 : aA0;
        const uint32_t dB = buf ? aB1 : aB0;
#pragma unroll
        for (int p = 0; p < 4; p++) {
            int idx = tid + p * 256;
            int r = idx >> 3, j = idx & 7;
            cp16(dA + sw((uint32_t)(r * 128 + j * 16)),
                 Ag + (size_t)(bm * 128 + r) * K3 + kt * 64 + j * 8);
        }
#pragma unroll
        for (int p = 0; p < 2; p++) {
            int idx = tid + p * 256;
            int r = idx >> 3, j = idx & 7;
            cp16(dB + sw((uint32_t)(r * 128 + j * 16)),
                 Bg + (size_t)(bn * 64 + r) * K3 + kt * 64 + j * 8);
        }
    };

    float acc[2][4][4];
#pragma unroll
    for (int a = 0; a < 2; a++)
#pragma unroll
        for (int b = 0; b < 4; b++)
#pragma unroll
            for (int c = 0; c < 4; c++) acc[a][b][c] = 0.f;

    const int lrow = lid & 15;
    const int lkb  = lid >> 4;

    issue_stage(0, 0); CP_COMMIT();
    issue_stage(1, 1); CP_COMMIT();

    for (int kt = 0; kt < NKT; kt++) {
        cp_wait<1>();
        __syncthreads();

        const uint32_t cA = (kt & 1) ? aA1 : aA0;
        const uint32_t cB = (kt & 1) ? aB1 : aB0;

#pragma unroll
        for (int ks = 0; ks < 4; ks++) {
            uint32_t afr[2][4], bfr[2][4];
#pragma unroll
            for (int mi = 0; mi < 2; mi++) {
                uint32_t o = (uint32_t)((wm * 32 + mi * 16 + lrow) * 128 +
                                        ks * 32 + lkb * 16);
                ldsm_x4(afr[mi], cA + sw(o));
            }
#pragma unroll
            for (int nb = 0; nb < 2; nb++) {
                uint32_t o = (uint32_t)((wn * 32 + nb * 16 + lrow) * 128 +
                                        ks * 32 + lkb * 16);
                ldsm_x4(bfr[nb], cB + sw(o));
            }
#pragma unroll
            for (int mi = 0; mi < 2; mi++)
#pragma unroll
                for (int ni = 0; ni < 4; ni++)
                    mma16816(acc[mi][ni], afr[mi],
                             bfr[ni >> 1][ni & 1], bfr[ni >> 1][(ni & 1) + 2]);
        }

        __syncthreads();
        if (kt + 2 < NKT) issue_stage(kt + 2, kt & 1);
        CP_COMMIT();
    }

    const int tg = lid >> 2;
    const int tc = (lid & 3) * 2;

    if (MODE == 1) {
#pragma unroll
        for (int mi = 0; mi < 2; mi++)
#pragma unroll
            for (int ni = 0; ni < 4; ni++) {
                int m0 = bm * 128 + wm * 32 + mi * 16 + tg;
                int n0 = bn * 64 + wn * 32 + ni * 8 + tc;
                *reinterpret_cast<float2*>(&Cout[(size_t)m0 * HID + n0]) =
                    make_float2(acc[mi][ni][0], acc[mi][ni][1]);
                *reinterpret_cast<float2*>(&Cout[(size_t)(m0 + 8) * HID + n0]) =
                    make_float2(acc[mi][ni][2], acc[mi][ni][3]);
            }
    } else {
#pragma unroll
        for (int mi = 0; mi < 2; mi++)
#pragma unroll
            for (int ni = 0; ni < 4; ni++)
#pragma unroll
                for (int q = 0; q < 4; q++) {
                    int m = bm * 128 + wm * 32 + mi * 16 + tg + (q >> 1) * 8;
                    int e = bn * 64 + wn * 32 + ni * 8 + tc + (q & 1);
                    float val = acc[mi][ni][q];
                    int b = m >> 11, s = m & 2047;
                    int region = e >> 10;
                    int e2 = e & 1023;
                    int h = e2 >> 6, d = e2 & 63;
                    int bh = b * HEADS + h;
                    if (region == 0) {
                        float qv = val * SCALE;
                        __nv_bfloat16 hv = __float2bfloat16(qv);
                        size_t off = ((size_t)bh * S_ + s) * HD + d;
                        g_Qh[off] = hv;
                        g_Ql[off] = __float2bfloat16(qv - __bfloat162float(hv));
                    } else if (region == 1) {
                        __nv_bfloat16 hv = __float2bfloat16(val);
                        size_t off = ((size_t)bh * S_ + s) * HD + d;
                        g_Kh[off] = hv;
                        g_Kl[off] = __float2bfloat16(val - __bfloat162float(hv));
                    } else {
                        __nv_bfloat16 hv = __float2bfloat16(val);
                        size_t off = ((size_t)bh * HD + d) * S_ + s;
                        g_Vth[off] = hv;
                        g_Vtl[off] = __float2bfloat16(val - __bfloat162float(hv));
                    }
                }
    }
}

// ---------------------------------------------------------------------------
// Tensor-core flash attention (R8, proven) + occupancy 3.
// ---------------------------------------------------------------------------
__device__ __forceinline__ void cp_tile64(uint32_t sdst,
                                          const __nv_bfloat16* g,
                                          int gstride, int tid)
{
#pragma unroll
    for (int p = 0; p < 4; p++) {
        int idx = tid + p * 128;
        int r = idx >> 3, j = idx & 7;
        cp16(sdst + sw((uint32_t)(r * 128 + j * 16)),
             g + (size_t)r * gstride + j * 8);
    }
}

__global__ __launch_bounds__(128, 3) void attn_mma()
{
    __shared__ __align__(128) __nv_bfloat16 sQh[4096], sQl[4096];
    __shared__ __align__(128) __nv_bfloat16 sKh[4096], sKl[4096];
    __shared__ __align__(128) __nv_bfloat16 sVh[4096], sVl[4096];

    const int tid = threadIdx.x;
    const int wid = tid >> 5;
    const int lid = tid & 31;
    const int qt = blockIdx.x;
    const int bh = blockIdx.y;
    const int b  = bh >> 4;
    const int h  = bh & 15;

    const int lrow = lid & 15;
    const int lkb  = lid >> 4;
    const int tg   = lid >> 2;
    const int tc   = (lid & 3) * 2;

    const uint32_t aQh = smem_u32(sQh), aQl = smem_u32(sQl);
    const uint32_t aKh = smem_u32(sKh), aKl = smem_u32(sKl);
    const uint32_t aVh = smem_u32(sVh), aVl = smem_u32(sVl);

    const __nv_bfloat16* Kh = g_Kh + (size_t)bh * S_ * HD;
    const __nv_bfloat16* Kl = g_Kl + (size_t)bh * S_ * HD;
    const __nv_bfloat16* Vh = g_Vth + (size_t)bh * HD * S_;
    const __nv_bfloat16* Vl = g_Vtl + (size_t)bh * HD * S_;

    const size_t qoff = ((size_t)bh * S_ + qt * 64) * HD;
    cp_tile64(aQh, g_Qh + qoff, HD, tid);
    cp_tile64(aQl, g_Ql + qoff, HD, tid);
    cp_tile64(aKh, Kh, HD, tid);
    cp_tile64(aKl, Kl, HD, tid);
    CP_COMMIT();
    cp_tile64(aVh, Vh, S_, tid);
    cp_tile64(aVl, Vl, S_, tid);
    CP_COMMIT();

    cp_wait<1>();
    __syncthreads();

    uint32_t qfh[4][4], qfl[4][4];
#pragma unroll
    for (int ks = 0; ks < 4; ks++) {
        uint32_t o = (uint32_t)((wid * 16 + lrow) * 128 + ks * 32 + lkb * 16);
        ldsm_x4(qfh[ks], aQh + sw(o));
        ldsm_x4(qfl[ks], aQl + sw(o));
    }

    float oacc[8][4];
#pragma unroll
    for (int t = 0; t < 8; t++)
#pragma unroll
        for (int c = 0; c < 4; c++) oacc[t][c] = 0.f;
    float m0 = -CUDART_INF_F, m1 = -CUDART_INF_F;
    float l0 = 0.f, l1 = 0.f;

    const int NT = S_ / 64;
    for (int kt = 0; kt < NT; kt++) {
        float sacc[8][4];
#pragma unroll
        for (int t = 0; t < 8; t++)
#pragma unroll
            for (int c = 0; c < 4; c++) sacc[t][c] = 0.f;

#pragma unroll
        for (int ks = 0; ks < 4; ks++) {
            uint32_t kbh[4][4], kbl[4][4];
#pragma unroll
            for (int nb = 0; nb < 4; nb++) {
                uint32_t o = (uint32_t)((nb * 16 + lrow) * 128 + ks * 32 + lkb * 16);
                ldsm_x4(kbh[nb], aKh + sw(o));
                ldsm_x4(kbl[nb], aKl + sw(o));
            }
#pragma unroll
            for (int nt = 0; nt < 8; nt++) {
                uint32_t bh0 = kbh[nt >> 1][nt & 1], bh1 = kbh[nt >> 1][(nt & 1) + 2];
                uint32_t bl0 = kbl[nt >> 1][nt & 1], bl1 = kbl[nt >> 1][(nt & 1) + 2];
                mma16816(sacc[nt], qfh[ks], bh0, bh1);
                mma16816(sacc[nt], qfh[ks], bl0, bl1);
                mma16816(sacc[nt], qfl[ks], bh0, bh1);
            }
        }

        __syncthreads();
        if (kt + 1 < NT) {
            cp_tile64(aKh, Kh + (size_t)(kt + 1) * 64 * HD, HD, tid);
            cp_tile64(aKl, Kl + (size_t)(kt + 1) * 64 * HD, HD, tid);
        }
        CP_COMMIT();

        float rm0 = -CUDART_INF_F, rm1 = -CUDART_INF_F;
#pragma unroll
        for (int t = 0; t < 8; t++) {
            rm0 = fmaxf(rm0, fmaxf(sacc[t][0], sacc[t][1]));
            rm1 = fmaxf(rm1, fmaxf(sacc[t][2], sacc[t][3]));
        }
        rm0 = fmaxf(rm0, __shfl_xor_sync(0xffffffffu, rm0, 1));
        rm0 = fmaxf(rm0, __shfl_xor_sync(0xffffffffu, rm0, 2));
        rm1 = fmaxf(rm1, __shfl_xor_sync(0xffffffffu, rm1, 1));
        rm1 = fmaxf(rm1, __shfl_xor_sync(0xffffffffu, rm1, 2));

        float mn0 = fmaxf(m0, rm0), mn1 = fmaxf(m1, rm1);
        float cr0 = __expf(m0 - mn0), cr1 = __expf(m1 - mn1);
        m0 = mn0; m1 = mn1;

        float rs0 = 0.f, rs1 = 0.f;
#pragma unroll
        for (int t = 0; t < 8; t++) {
            sacc[t][0] = __expf(sacc[t][0] - mn0);
            sacc[t][1] = __expf(sacc[t][1] - mn0);
            sacc[t][2] = __expf(sacc[t][2] - mn1);
            sacc[t][3] = __expf(sacc[t][3] - mn1);
            rs0 += sacc[t][0] + sacc[t][1];
            rs1 += sacc[t][2] + sacc[t][3];
        }
        rs0 += __shfl_xor_sync(0xffffffffu, rs0, 1);
        rs0 += __shfl_xor_sync(0xffffffffu, rs0, 2);
        rs1 += __shfl_xor_sync(0xffffffffu, rs1, 1);
        rs1 += __shfl_xor_sync(0xffffffffu, rs1, 2);
        l0 = l0 * cr0 + rs0;
        l1 = l1 * cr1 + rs1;

#pragma unroll
        for (int t = 0; t < 8; t++) {
            oacc[t][0] *= cr0; oacc[t][1] *= cr0;
            oacc[t][2] *= cr1; oacc[t][3] *= cr1;
        }

        uint32_t pah[4][4], pal[4][4];
#pragma unroll
        for (int ks = 0; ks < 4; ks++) {
            const int t0 = 2 * ks, t1 = 2 * ks + 1;
            float ph[8], pl[8];
            const float pv[8] = {sacc[t0][0], sacc[t0][1], sacc[t0][2], sacc[t0][3],
                                 sacc[t1][0], sacc[t1][1], sacc[t1][2], sacc[t1][3]};
#pragma unroll
            for (int e = 0; e < 8; e++) {
                __nv_bfloat16 hb = __float2bfloat16(pv[e]);
                ph[e] = __bfloat162float(hb);
                pl[e] = pv[e] - ph[e];
            }
            pah[ks][0] = pack_bf16(ph[0], ph[1]);
            pah[ks][1] = pack_bf16(ph[2], ph[3]);
            pah[ks][2] = pack_bf16(ph[4], ph[5]);
            pah[ks][3] = pack_bf16(ph[6], ph[7]);
            pal[ks][0] = pack_bf16(pl[0], pl[1]);
            pal[ks][1] = pack_bf16(pl[2], pl[3]);
            pal[ks][2] = pack_bf16(pl[4], pl[5]);
            pal[ks][3] = pack_bf16(pl[6], pl[7]);
        }

        cp_wait<1>();
        __syncthreads();

#pragma unroll
        for (int ks = 0; ks < 4; ks++) {
            uint32_t vbh[4][4], vbl[4][4];
#pragma unroll
            for (int nb = 0; nb < 4; nb++) {
                uint32_t o = (uint32_t)((nb * 16 + lrow) * 128 + ks * 32 + lkb * 16);
                ldsm_x4(vbh[nb], aVh + sw(o));
                ldsm_x4(vbl[nb], aVl + sw(o));
            }
#pragma unroll
            for (int nt = 0; nt < 8; nt++) {
                uint32_t bh0 = vbh[nt >> 1][nt & 1], bh1 = vbh[nt >> 1][(nt & 1) + 2];
                uint32_t bl0 = vbl[nt >> 1][nt & 1], bl1 = vbl[nt >> 1][(nt & 1) + 2];
                mma16816(oacc[nt], pah[ks], bh0, bh1);
                mma16816(oacc[nt], pah[ks], bl0, bl1);
                mma16816(oacc[nt], pal[ks], bh0, bh1);
            }
        }

        __syncthreads();
        if (kt + 1 < NT) {
            cp_tile64(aVh, Vh + (size_t)(kt + 1) * 64, S_, tid);
            cp_tile64(aVl, Vl + (size_t)(kt + 1) * 64, S_, tid);
        }
        CP_COMMIT();
        cp_wait<1>();
        __syncthreads();
    }

    const float inv0 = 1.f / l0, inv1 = 1.f / l1;
    const int r0 = qt * 64 + wid * 16 + tg;
    const int m0row = b * S_ + r0;
#pragma unroll
    for (int nt = 0; nt < 8; nt++) {
        int col = h * 64 + nt * 8 + tc;
#pragma unroll
        for (int q = 0; q < 4; q++) {
            int m = m0row + (q >> 1) * 8;
            int k = col + (q & 1);
            float val = oacc[nt][q] * ((q < 2) ? inv0 : inv1);
            __nv_bfloat16 hv = __float2bfloat16(val);
            size_t base = (size_t)m * K3 + k;
            g_Oe[base]        = hv;
            g_Oe[base + 1024] = hv;
            g_Oe[base + 2048] = __float2bfloat16(val - __bfloat162float(hv));
        }
    }
}

// ---------------------------------------------------------------------------
extern "C" void kernel_launch(void* const* d_in, const int* in_sizes, int n_in,
                              void* d_out, int out_size)
{
    const float* x    = (const float*)d_in[0];
    const float* wqkv = (const float*)d_in[1];
    const float* wout = (const float*)d_in[2];
    for (int i = 0; i < n_in; i++) {
        if      (in_sizes[i] == 4194304) x    = (const float*)d_in[i];
        else if (in_sizes[i] == 3145728) wqkv = (const float*)d_in[i];
        else if (in_sizes[i] == 1048576) wout = (const float*)d_in[i];
    }
    float* out = (float*)d_out;

    convert_all<<<2048, 256>>>(x, wqkv, wout);

    mma_gemm<0><<<dim3(3 * HID / 64, M_TOT / 128), 256>>>(nullptr);

    attn_mma<<<dim3(S_ / 64, B_ * HEADS), 128>>>();

    mma_gemm<1><<<dim3(HID / 64, M_TOT / 128), 256>>>(out);
}